// round 1
// baseline (speedup 1.0000x reference)
#include <cuda_runtime.h>
#include <math.h>

#define BATCH 2
#define NHEAD 16
#define SEQ   2048
#define EMB   1024
#define HDIM  64
#define GATE_EPS 1e-4f

// ---------------- scratch (device globals; no allocations allowed) -------------
__device__ float g_Q[BATCH * NHEAD * SEQ * HDIM];   // 16 MB
__device__ float g_K[BATCH * NHEAD * SEQ * HDIM];   // 16 MB
__device__ float g_V[BATCH * NHEAD * SEQ * HDIM];   // 16 MB
__device__ float g_C[BATCH * NHEAD * SEQ * HDIM];   // 16 MB (context, gate-scaled)
__device__ float g_P[134217728];                    // [B,H,S,S] scores/probs, 512 MB

// =====================================================================
// Kernel 1: QKV projection.  Y[b,h,s,d] = sum_e X[b,s,e] * W[h,e,d]
// GEMM: M = B*S = 4096, N = H*D = 1024, K = E = 1024.  blockIdx.z selects q/k/v.
// Tiles: 128x128x16, 256 threads, 8x8 per-thread microtile.
// =====================================================================
__global__ __launch_bounds__(256) void qkv_kernel(
    const float* __restrict__ X,
    const float* __restrict__ Wq,
    const float* __restrict__ Wk,
    const float* __restrict__ Wv)
{
    __shared__ float As[16][132];
    __shared__ float Bs[16][132];

    const int bm = blockIdx.x * 128;
    const int bn = blockIdx.y * 128;
    const int wsel = blockIdx.z;
    const float* __restrict__ W = (wsel == 0) ? Wq : (wsel == 1) ? Wk : Wv;
    float* __restrict__ Y = (wsel == 0) ? g_Q : (wsel == 1) ? g_K : g_V;

    const int tid = threadIdx.x;
    const int tx = tid & 15, ty = tid >> 4;
    const int m0 = ty * 8, n0 = tx * 8;

    float acc[8][8];
#pragma unroll
    for (int i = 0; i < 8; i++)
#pragma unroll
        for (int j = 0; j < 8; j++) acc[i][j] = 0.0f;

    for (int k0 = 0; k0 < EMB; k0 += 16) {
        // A tile: X[bm+m][k0+k]
#pragma unroll
        for (int i = 0; i < 8; i++) {
            int idx = tid + i * 256;
            int m = idx >> 4, k = idx & 15;
            As[k][m] = X[(size_t)(bm + m) * EMB + (k0 + k)];
        }
        // B tile: W[h][k0+k][d] with n = h*64 + d
#pragma unroll
        for (int i = 0; i < 8; i++) {
            int idx = tid + i * 256;
            int k = idx >> 7, nn = idx & 127;
            int n = bn + nn;
            int h = n >> 6, d = n & 63;
            Bs[k][nn] = W[(size_t)h * EMB * HDIM + (size_t)(k0 + k) * HDIM + d];
        }
        __syncthreads();
#pragma unroll
        for (int kk = 0; kk < 16; kk++) {
            float a[8], b[8];
            *(float4*)&a[0] = *(const float4*)&As[kk][m0];
            *(float4*)&a[4] = *(const float4*)&As[kk][m0 + 4];
            *(float4*)&b[0] = *(const float4*)&Bs[kk][n0];
            *(float4*)&b[4] = *(const float4*)&Bs[kk][n0 + 4];
#pragma unroll
            for (int i = 0; i < 8; i++)
#pragma unroll
                for (int j = 0; j < 8; j++)
                    acc[i][j] = fmaf(a[i], b[j], acc[i][j]);
        }
        __syncthreads();
    }

#pragma unroll
    for (int i = 0; i < 8; i++) {
        int m = bm + m0 + i;
        int bb = m >> 11, s = m & (SEQ - 1);
#pragma unroll
        for (int j = 0; j < 8; j++) {
            int n = bn + n0 + j;
            int h = n >> 6, d = n & 63;
            Y[(((size_t)bb * NHEAD + h) * SEQ + s) * HDIM + d] = acc[i][j];
        }
    }
}

// =====================================================================
// Kernel 2: scores[b,h,s,t] = (Q[b,h,s,:] . K[b,h,t,:]) / 8 + mask[b,t]
// Per (b,h): GEMM M=N=2048, K=64.  Tiles 128x128x16.
// =====================================================================
__global__ __launch_bounds__(256) void scores_kernel(const float* __restrict__ mask)
{
    __shared__ float As[16][132];
    __shared__ float Bs[16][132];

    const int bm = blockIdx.x * 128;
    const int bn = blockIdx.y * 128;
    const int bh = blockIdx.z;            // b*H + h
    const int bb = bh >> 4;
    const float* __restrict__ Q = g_Q + (size_t)bh * SEQ * HDIM;
    const float* __restrict__ K = g_K + (size_t)bh * SEQ * HDIM;

    const int tid = threadIdx.x;
    const int tx = tid & 15, ty = tid >> 4;
    const int m0 = ty * 8, n0 = tx * 8;

    float acc[8][8];
#pragma unroll
    for (int i = 0; i < 8; i++)
#pragma unroll
        for (int j = 0; j < 8; j++) acc[i][j] = 0.0f;

    for (int k0 = 0; k0 < HDIM; k0 += 16) {
#pragma unroll
        for (int i = 0; i < 8; i++) {
            int idx = tid + i * 256;
            int m = idx >> 4, k = idx & 15;
            As[k][m] = Q[(size_t)(bm + m) * HDIM + (k0 + k)];
        }
#pragma unroll
        for (int i = 0; i < 8; i++) {
            int idx = tid + i * 256;
            int n = idx >> 4, k = idx & 15;
            Bs[k][n] = K[(size_t)(bn + n) * HDIM + (k0 + k)];
        }
        __syncthreads();
#pragma unroll
        for (int kk = 0; kk < 16; kk++) {
            float a[8], b[8];
            *(float4*)&a[0] = *(const float4*)&As[kk][m0];
            *(float4*)&a[4] = *(const float4*)&As[kk][m0 + 4];
            *(float4*)&b[0] = *(const float4*)&Bs[kk][n0];
            *(float4*)&b[4] = *(const float4*)&Bs[kk][n0 + 4];
#pragma unroll
            for (int i = 0; i < 8; i++)
#pragma unroll
                for (int j = 0; j < 8; j++)
                    acc[i][j] = fmaf(a[i], b[j], acc[i][j]);
        }
        __syncthreads();
    }

#pragma unroll
    for (int i = 0; i < 8; i++) {
        int m = bm + m0 + i;
        size_t rowoff = ((size_t)bh * SEQ + m) * SEQ;
#pragma unroll
        for (int j = 0; j < 8; j++) {
            int n = bn + n0 + j;
            g_P[rowoff + n] = acc[i][j] * 0.125f + mask[bb * SEQ + n];
        }
    }
}

// =====================================================================
// Kernel 3: row softmax, in place in g_P.  One warp per row of 2048.
// =====================================================================
__global__ __launch_bounds__(256) void softmax_kernel()
{
    const int warp = threadIdx.x >> 5;
    const int lane = threadIdx.x & 31;
    const size_t row = (size_t)blockIdx.x * 8 + warp;   // rows = B*H*S = 65536
    float* __restrict__ p = g_P + row * SEQ;

    float v[64];
    float m = -INFINITY;
#pragma unroll
    for (int i = 0; i < 64; i++) {
        v[i] = p[lane + i * 32];
        m = fmaxf(m, v[i]);
    }
#pragma unroll
    for (int o = 16; o > 0; o >>= 1) m = fmaxf(m, __shfl_xor_sync(0xffffffffu, m, o));

    float sum = 0.0f;
#pragma unroll
    for (int i = 0; i < 64; i++) {
        v[i] = expf(v[i] - m);
        sum += v[i];
    }
#pragma unroll
    for (int o = 16; o > 0; o >>= 1) sum += __shfl_xor_sync(0xffffffffu, sum, o);

    const float inv = 1.0f / sum;
#pragma unroll
    for (int i = 0; i < 64; i++) p[lane + i * 32] = v[i] * inv;
}

// =====================================================================
// Kernel 4: context[b,h,s,d] = eff_gate[h] * sum_t P[b,h,s,t] * V[b,h,t,d]
// Per (b,h): GEMM M=2048, N=64, K=2048. Tiles 128x64x16, microtile 8x4.
// =====================================================================
__global__ __launch_bounds__(256) void pv_kernel(const float* __restrict__ gate)
{
    __shared__ float As[16][132];
    __shared__ float Bs[16][68];

    const int bm = blockIdx.x * 128;
    const int bh = blockIdx.y;            // b*H + h
    const int h = bh & 15;
    const float* __restrict__ P = g_P + (size_t)bh * SEQ * SEQ;
    const float* __restrict__ V = g_V + (size_t)bh * SEQ * HDIM;

    const int tid = threadIdx.x;
    const int tx = tid & 15, ty = tid >> 4;
    const int m0 = ty * 8, n0 = tx * 4;

    float acc[8][4];
#pragma unroll
    for (int i = 0; i < 8; i++)
#pragma unroll
        for (int j = 0; j < 4; j++) acc[i][j] = 0.0f;

    for (int k0 = 0; k0 < SEQ; k0 += 16) {
#pragma unroll
        for (int i = 0; i < 8; i++) {
            int idx = tid + i * 256;
            int m = idx >> 4, k = idx & 15;
            As[k][m] = P[(size_t)(bm + m) * SEQ + (k0 + k)];
        }
#pragma unroll
        for (int i = 0; i < 4; i++) {
            int idx = tid + i * 256;
            int k = idx >> 6, n = idx & 63;
            Bs[k][n] = V[(size_t)(k0 + k) * HDIM + n];
        }
        __syncthreads();
#pragma unroll
        for (int kk = 0; kk < 16; kk++) {
            float a[8], b[4];
            *(float4*)&a[0] = *(const float4*)&As[kk][m0];
            *(float4*)&a[4] = *(const float4*)&As[kk][m0 + 4];
            *(float4*)&b[0] = *(const float4*)&Bs[kk][n0];
#pragma unroll
            for (int i = 0; i < 8; i++)
#pragma unroll
                for (int j = 0; j < 4; j++)
                    acc[i][j] = fmaf(a[i], b[j], acc[i][j]);
        }
        __syncthreads();
    }

    float g = gate[h];
    float eff = (g >= GATE_EPS) ? g : 0.0f;
#pragma unroll
    for (int i = 0; i < 8; i++) {
        int m = bm + m0 + i;
        size_t base = ((size_t)bh * SEQ + m) * HDIM;
#pragma unroll
        for (int j = 0; j < 4; j++)
            g_C[base + n0 + j] = acc[i][j] * eff;
    }
}

// =====================================================================
// Kernel 5: out[b,s,e] = (1/denom) * sum_{h,d} C[b,h,s,d] * Wo[h,d,e]
// GEMM: M = B*S = 4096, N = E = 1024, K = H*D = 1024.
// Wo stacked over (h,d) is contiguous [1024,1024] row-major.
// =====================================================================
__global__ __launch_bounds__(256) void oproj_kernel(
    const float* __restrict__ Wo,
    const float* __restrict__ gate,
    float* __restrict__ out)
{
    __shared__ float As[16][132];
    __shared__ float Bs[16][132];

    const int bm = blockIdx.x * 128;
    const int bn = blockIdx.y * 128;

    const int tid = threadIdx.x;
    const int tx = tid & 15, ty = tid >> 4;
    const int m0 = ty * 8, n0 = tx * 8;

    float acc[8][8];
#pragma unroll
    for (int i = 0; i < 8; i++)
#pragma unroll
        for (int j = 0; j < 8; j++) acc[i][j] = 0.0f;

    for (int k0 = 0; k0 < EMB; k0 += 16) {
        // A tile: C[b][h][s][d] with m=(b,s), k=(h,d); BK=16 never crosses a head
#pragma unroll
        for (int i = 0; i < 8; i++) {
            int idx = tid + i * 256;
            int m = idx >> 4, k = idx & 15;
            int gm = bm + m;
            int bb = gm >> 11, s = gm & (SEQ - 1);
            int gk = k0 + k;
            int h = gk >> 6, d = gk & 63;
            As[k][m] = g_C[(((size_t)bb * NHEAD + h) * SEQ + s) * HDIM + d];
        }
        // B tile: Wo_flat[k][n], row-major [1024,1024]
#pragma unroll
        for (int i = 0; i < 8; i++) {
            int idx = tid + i * 256;
            int k = idx >> 7, nn = idx & 127;
            Bs[k][nn] = Wo[(size_t)(k0 + k) * EMB + bn + nn];
        }
        __syncthreads();
#pragma unroll
        for (int kk = 0; kk < 16; kk++) {
            float a[8], b[8];
            *(float4*)&a[0] = *(const float4*)&As[kk][m0];
            *(float4*)&a[4] = *(const float4*)&As[kk][m0 + 4];
            *(float4*)&b[0] = *(const float4*)&Bs[kk][n0];
            *(float4*)&b[4] = *(const float4*)&Bs[kk][n0 + 4];
#pragma unroll
            for (int i = 0; i < 8; i++)
#pragma unroll
                for (int j = 0; j < 8; j++)
                    acc[i][j] = fmaf(a[i], b[j], acc[i][j]);
        }
        __syncthreads();
    }

    // Final rescale: denom = max(1, active/16) when any head active (strict > eps)
    int cnt = 0;
#pragma unroll
    for (int i = 0; i < NHEAD; i++) cnt += (gate[i] > GATE_EPS) ? 1 : 0;
    float denom = fmaxf(1.0f, (float)cnt / (float)NHEAD);
    float scale = (cnt > 0) ? (1.0f / denom) : 1.0f;

#pragma unroll
    for (int i = 0; i < 8; i++) {
        size_t m = (size_t)(bm + m0 + i);
#pragma unroll
        for (int j = 0; j < 8; j++)
            out[m * EMB + bn + n0 + j] = acc[i][j] * scale;
    }
}

// =====================================================================
extern "C" void kernel_launch(void* const* d_in, const int* in_sizes, int n_in,
                              void* d_out, int out_size)
{
    const float* X    = (const float*)d_in[0];   // hidden_states [B,S,E]
    const float* mask = (const float*)d_in[1];   // attention_mask [B,1,1,S]
    const float* Wq   = (const float*)d_in[2];   // [H,E,D]
    const float* Wk   = (const float*)d_in[3];   // [H,E,D]
    const float* Wv   = (const float*)d_in[4];   // [H,E,D]
    const float* Wo   = (const float*)d_in[5];   // [H,D,E]
    const float* gate = (const float*)d_in[6];   // [H]
    float* out = (float*)d_out;                  // [B,S,E] fp32

    qkv_kernel<<<dim3(32, 8, 3), 256>>>(X, Wq, Wk, Wv);
    scores_kernel<<<dim3(16, 16, 32), 256>>>(mask);
    softmax_kernel<<<8192, 256>>>();
    pv_kernel<<<dim3(16, 32), 256>>>(gate);
    oproj_kernel<<<dim3(32, 8), 256>>>(Wo, gate, out);
}

// round 2
// speedup vs baseline: 2.3684x; 2.3684x over previous
#include <cuda_runtime.h>
#include <cuda_bf16.h>
#include <math.h>

#define BATCH 2
#define NHEAD 16
#define SEQ   2048
#define EMB   1024
#define HDIM  64
#define GATE_EPS 1e-4f

typedef unsigned int u32;

// ------------------ scratch (bf16 hi/lo splits; ~95 MB total) ------------------
__device__ __nv_bfloat16 g_Xh[4096 * 1024];
__device__ __nv_bfloat16 g_Xl[4096 * 1024];
// W: slot 0..2 = Wq/Wk/Wv transposed to [n=(h,d)][k=e]; slot 3 = Wo^T [n=e][k=(h,d)]
__device__ __nv_bfloat16 g_Wh[4 * 1024 * 1024];
__device__ __nv_bfloat16 g_Wl[4 * 1024 * 1024];
// Q,K,V: [b*16+h][s][d] bf16 hi/lo
__device__ __nv_bfloat16 g_Qh[32 * 2048 * 64];
__device__ __nv_bfloat16 g_Ql[32 * 2048 * 64];
__device__ __nv_bfloat16 g_Kh[32 * 2048 * 64];
__device__ __nv_bfloat16 g_Kl[32 * 2048 * 64];
__device__ __nv_bfloat16 g_Vh[32 * 2048 * 64];
__device__ __nv_bfloat16 g_Vl[32 * 2048 * 64];
// context: [b][s][h*64+d] bf16 hi/lo
__device__ __nv_bfloat16 g_Ch[4096 * 1024];
__device__ __nv_bfloat16 g_Cl[4096 * 1024];

// ------------------------------- helpers ---------------------------------------
__device__ __forceinline__ void split_pair(float x, float y, u32 &hi, u32 &lo) {
    __nv_bfloat16 hx = __float2bfloat16(x);
    __nv_bfloat16 hy = __float2bfloat16(y);
    __nv_bfloat16 lx = __float2bfloat16(x - __bfloat162float(hx));
    __nv_bfloat16 ly = __float2bfloat16(y - __bfloat162float(hy));
    __nv_bfloat162 hp = __halves2bfloat162(hx, hy);
    __nv_bfloat162 lp = __halves2bfloat162(lx, ly);
    hi = *reinterpret_cast<u32*>(&hp);
    lo = *reinterpret_cast<u32*>(&lp);
}

__device__ __forceinline__ void mma16816(float* d, u32 a0, u32 a1, u32 a2, u32 a3,
                                         u32 b0, u32 b1) {
    asm volatile(
        "mma.sync.aligned.m16n8k16.row.col.f32.bf16.bf16.f32 "
        "{%0,%1,%2,%3}, {%4,%5,%6,%7}, {%8,%9}, {%0,%1,%2,%3};\n"
        : "+f"(d[0]), "+f"(d[1]), "+f"(d[2]), "+f"(d[3])
        : "r"(a0), "r"(a1), "r"(a2), "r"(a3), "r"(b0), "r"(b1));
}

// ================================================================================
// prep_x: split hidden_states fp32 -> hi/lo bf16 (same layout [4096][1024])
// ================================================================================
__global__ __launch_bounds__(256) void prep_x_kernel(const float* __restrict__ X) {
    int idx = blockIdx.x * 256 + threadIdx.x;
    float x = X[idx];
    __nv_bfloat16 h = __float2bfloat16(x);
    g_Xh[idx] = h;
    g_Xl[idx] = __float2bfloat16(x - __bfloat162float(h));
}

// ================================================================================
// transpose W_q/W_k/W_v: per head, [E][D] -> [D][E] (so B rows = n, contiguous k)
// grid (2, 32, 48), block (32, 8)
// ================================================================================
__global__ void transpose_wqkv_kernel(const float* __restrict__ Wq,
                                      const float* __restrict__ Wk,
                                      const float* __restrict__ Wv) {
    __shared__ float tile[32][33];
    int z = blockIdx.z;
    int w = z >> 4, h = z & 15;
    const float* in = ((w == 0) ? Wq : (w == 1) ? Wk : Wv) + (size_t)h * EMB * HDIM;
    __nv_bfloat16* oh = g_Wh + (size_t)w * 1048576 + (size_t)h * 64 * 1024;
    __nv_bfloat16* ol = g_Wl + (size_t)w * 1048576 + (size_t)h * 64 * 1024;
    int e0 = blockIdx.y * 32, d0 = blockIdx.x * 32;
    for (int i = threadIdx.y; i < 32; i += 8)
        tile[i][threadIdx.x] = in[(size_t)(e0 + i) * HDIM + d0 + threadIdx.x];
    __syncthreads();
    for (int i = threadIdx.y; i < 32; i += 8) {
        float v = tile[threadIdx.x][i];           // = in[e0+x][d0+i]
        __nv_bfloat16 hh = __float2bfloat16(v);
        oh[(size_t)(d0 + i) * 1024 + e0 + threadIdx.x] = hh;
        ol[(size_t)(d0 + i) * 1024 + e0 + threadIdx.x] =
            __float2bfloat16(v - __bfloat162float(hh));
    }
}

// ================================================================================
// transpose W_o: [1024(k)][1024(n)] -> [n][k] into slot 3. grid (32,32), block (32,8)
// ================================================================================
__global__ void transpose_wo_kernel(const float* __restrict__ Wo) {
    __shared__ float tile[32][33];
    __nv_bfloat16* oh = g_Wh + 3u * 1048576;
    __nv_bfloat16* ol = g_Wl + 3u * 1048576;
    int k0 = blockIdx.y * 32, n0 = blockIdx.x * 32;
    for (int i = threadIdx.y; i < 32; i += 8)
        tile[i][threadIdx.x] = Wo[(size_t)(k0 + i) * 1024 + n0 + threadIdx.x];
    __syncthreads();
    for (int i = threadIdx.y; i < 32; i += 8) {
        float v = tile[threadIdx.x][i];           // = Wo[k0+x][n0+i]
        __nv_bfloat16 hh = __float2bfloat16(v);
        oh[(size_t)(n0 + i) * 1024 + k0 + threadIdx.x] = hh;
        ol[(size_t)(n0 + i) * 1024 + k0 + threadIdx.x] =
            __float2bfloat16(v - __bfloat162float(hh));
    }
}

// ================================================================================
// QKV GEMM (split-bf16 mma): M=4096, N=1024, K=1024; z selects Q/K/V.
// CTA 128x128, BK=32, 8 warps (4x2), warp tile 32x64.
// Epilogue: hi/lo bf16 to g_{Q,K,V}{h,l} at [b*16+h][s][d].
// ================================================================================
__global__ __launch_bounds__(256) void qkv_gemm_kernel() {
    __shared__ __nv_bfloat16 Ah[128][40], Al[128][40], Bh[128][40], Bl[128][40];

    const int bm = blockIdx.x * 128;
    const int bn = blockIdx.y * 128;
    const int z  = blockIdx.z;

    const __nv_bfloat16* __restrict__ pAh = g_Xh;
    const __nv_bfloat16* __restrict__ pAl = g_Xl;
    const __nv_bfloat16* __restrict__ pBh = g_Wh + (size_t)z * 1048576;
    const __nv_bfloat16* __restrict__ pBl = g_Wl + (size_t)z * 1048576;

    const int tid = threadIdx.x;
    const int lane = tid & 31, warp = tid >> 5;
    const int wr = warp & 3, wc = warp >> 2;
    const int g = lane >> 2, c = lane & 3;

    float acc[2][8][4];
#pragma unroll
    for (int mt = 0; mt < 2; mt++)
#pragma unroll
        for (int j = 0; j < 8; j++)
#pragma unroll
            for (int q = 0; q < 4; q++) acc[mt][j][q] = 0.0f;

    for (int k0 = 0; k0 < 1024; k0 += 32) {
#pragma unroll
        for (int i = 0; i < 2; i++) {
            int idx = tid * 2 + i;            // 0..511
            int row = idx >> 2, seg = idx & 3;
            *(uint4*)&Ah[row][seg * 8] = *(const uint4*)&pAh[(size_t)(bm + row) * 1024 + k0 + seg * 8];
            *(uint4*)&Al[row][seg * 8] = *(const uint4*)&pAl[(size_t)(bm + row) * 1024 + k0 + seg * 8];
            *(uint4*)&Bh[row][seg * 8] = *(const uint4*)&pBh[(size_t)(bn + row) * 1024 + k0 + seg * 8];
            *(uint4*)&Bl[row][seg * 8] = *(const uint4*)&pBl[(size_t)(bn + row) * 1024 + k0 + seg * 8];
        }
        __syncthreads();
#pragma unroll
        for (int kk = 0; kk < 2; kk++) {
            const int col = kk * 16 + 2 * c;
            u32 ah[2][4], al[2][4];
#pragma unroll
            for (int mt = 0; mt < 2; mt++) {
                int r = wr * 32 + mt * 16 + g;
                ah[mt][0] = *(u32*)&Ah[r][col];
                ah[mt][1] = *(u32*)&Ah[r + 8][col];
                ah[mt][2] = *(u32*)&Ah[r][col + 8];
                ah[mt][3] = *(u32*)&Ah[r + 8][col + 8];
                al[mt][0] = *(u32*)&Al[r][col];
                al[mt][1] = *(u32*)&Al[r + 8][col];
                al[mt][2] = *(u32*)&Al[r][col + 8];
                al[mt][3] = *(u32*)&Al[r + 8][col + 8];
            }
#pragma unroll
            for (int j = 0; j < 8; j++) {
                int n = wc * 64 + j * 8 + g;
                u32 bh0 = *(u32*)&Bh[n][col], bh1 = *(u32*)&Bh[n][col + 8];
                u32 bl0 = *(u32*)&Bl[n][col], bl1 = *(u32*)&Bl[n][col + 8];
#pragma unroll
                for (int mt = 0; mt < 2; mt++) {
                    mma16816(acc[mt][j], ah[mt][0], ah[mt][1], ah[mt][2], ah[mt][3], bh0, bh1);
                    mma16816(acc[mt][j], ah[mt][0], ah[mt][1], ah[mt][2], ah[mt][3], bl0, bl1);
                    mma16816(acc[mt][j], al[mt][0], al[mt][1], al[mt][2], al[mt][3], bh0, bh1);
                }
            }
        }
        __syncthreads();
    }

    __nv_bfloat16* outh = (z == 0) ? g_Qh : (z == 1) ? g_Kh : g_Vh;
    __nv_bfloat16* outl = (z == 0) ? g_Ql : (z == 1) ? g_Kl : g_Vl;

#pragma unroll
    for (int mt = 0; mt < 2; mt++) {
        int row = bm + wr * 32 + mt * 16 + g;
        int b = row >> 11, s = row & (SEQ - 1);
#pragma unroll
        for (int j = 0; j < 8; j++) {
            int n0 = bn + wc * 64 + j * 8 + 2 * c;
            int h = n0 >> 6, d = n0 & 63;
            size_t base = (((size_t)(b * 16 + h)) * SEQ + s) * 64 + d;
            u32 hp, lp;
            split_pair(acc[mt][j][0], acc[mt][j][1], hp, lp);
            *(u32*)&outh[base] = hp;
            *(u32*)&outl[base] = lp;
            size_t base8 = base + 8 * 64;     // row + 8 (same b, same h)
            split_pair(acc[mt][j][2], acc[mt][j][3], hp, lp);
            *(u32*)&outh[base8] = hp;
            *(u32*)&outl[base8] = lp;
        }
    }
}

// ================================================================================
// Fused flash attention (split-bf16 mma), per (b,h), 128 Q rows per CTA.
// grid (16, 32), 256 threads, dynamic smem ~106.5 KB.
// Output: gated context as hi/lo bf16 at [b][s][h*64+d].
// ================================================================================
#define QK_STRIDE 72
#define V_STRIDE  136
#define FLASH_SMEM 109056

__global__ __launch_bounds__(256, 1) void flash_kernel(const float* __restrict__ mask,
                                                       const float* __restrict__ gate) {
    extern __shared__ char smem_raw[];
    __nv_bfloat16* sQh = (__nv_bfloat16*)smem_raw;
    __nv_bfloat16* sQl = sQh + 9216;
    __nv_bfloat16* sKh = sQh + 18432;
    __nv_bfloat16* sKl = sQh + 27648;
    __nv_bfloat16* sVh = sQh + 36864;
    __nv_bfloat16* sVl = sQh + 45568;
    float* maskS = (float*)(smem_raw + 108544);

    const int bm = blockIdx.x * 128;
    const int bh = blockIdx.y;
    const int b = bh >> 4, h = bh & 15;

    const int tid = threadIdx.x;
    const int lane = tid & 31, warp = tid >> 5;
    const int g = lane >> 2, c = lane & 3;
    const int mr = warp * 16;

    // load Q tile (hi/lo)
    const size_t qbase = ((size_t)bh * SEQ + bm) * 64;
#pragma unroll
    for (int i = 0; i < 4; i++) {
        int idx = tid + i * 256;                  // 0..1023
        int row = idx >> 3, seg = idx & 7;
        *(uint4*)&sQh[row * QK_STRIDE + seg * 8] = *(const uint4*)&g_Qh[qbase + (size_t)row * 64 + seg * 8];
        *(uint4*)&sQl[row * QK_STRIDE + seg * 8] = *(const uint4*)&g_Ql[qbase + (size_t)row * 64 + seg * 8];
    }

    float o[8][4];
#pragma unroll
    for (int j = 0; j < 8; j++)
#pragma unroll
        for (int q = 0; q < 4; q++) o[j][q] = 0.0f;
    float m0 = -1e30f, m1 = -1e30f, l0 = 0.0f, l1 = 0.0f;

    for (int it = 0; it < 16; it++) {
        const int t0 = it * 128;
        const size_t kbase = ((size_t)bh * SEQ + t0) * 64;
        __syncthreads();   // protect smem reuse from previous iteration
#pragma unroll
        for (int i = 0; i < 4; i++) {
            int idx = tid + i * 256;
            int row = idx >> 3, seg = idx & 7;
            *(uint4*)&sKh[row * QK_STRIDE + seg * 8] = *(const uint4*)&g_Kh[kbase + (size_t)row * 64 + seg * 8];
            *(uint4*)&sKl[row * QK_STRIDE + seg * 8] = *(const uint4*)&g_Kl[kbase + (size_t)row * 64 + seg * 8];
        }
        // V: load [t][d] pairs, store transposed [d][t]
#pragma unroll
        for (int i = 0; i < 16; i++) {
            int idx = tid + i * 256;              // 0..4095
            int t = idx >> 5, cc = idx & 31;      // d pair = 2cc
            __nv_bfloat162 vh2 = *(const __nv_bfloat162*)&g_Vh[kbase + (size_t)t * 64 + cc * 2];
            __nv_bfloat162 vl2 = *(const __nv_bfloat162*)&g_Vl[kbase + (size_t)t * 64 + cc * 2];
            sVh[(2 * cc) * V_STRIDE + t] = vh2.x;
            sVh[(2 * cc + 1) * V_STRIDE + t] = vh2.y;
            sVl[(2 * cc) * V_STRIDE + t] = vl2.x;
            sVl[(2 * cc + 1) * V_STRIDE + t] = vl2.y;
        }
        if (tid < 128) maskS[tid] = mask[b * SEQ + t0 + tid];
        __syncthreads();

        // ---- S = Q K^T (split) ----
        float s[16][4];
#pragma unroll
        for (int j = 0; j < 16; j++)
#pragma unroll
            for (int q = 0; q < 4; q++) s[j][q] = 0.0f;

#pragma unroll
        for (int kk = 0; kk < 4; kk++) {
            const int col = kk * 16 + 2 * c;
            u32 qh0 = *(u32*)&sQh[(mr + g) * QK_STRIDE + col];
            u32 qh1 = *(u32*)&sQh[(mr + g + 8) * QK_STRIDE + col];
            u32 qh2 = *(u32*)&sQh[(mr + g) * QK_STRIDE + col + 8];
            u32 qh3 = *(u32*)&sQh[(mr + g + 8) * QK_STRIDE + col + 8];
            u32 ql0 = *(u32*)&sQl[(mr + g) * QK_STRIDE + col];
            u32 ql1 = *(u32*)&sQl[(mr + g + 8) * QK_STRIDE + col];
            u32 ql2 = *(u32*)&sQl[(mr + g) * QK_STRIDE + col + 8];
            u32 ql3 = *(u32*)&sQl[(mr + g + 8) * QK_STRIDE + col + 8];
#pragma unroll
            for (int j = 0; j < 16; j++) {
                int n = j * 8 + g;
                u32 kh0 = *(u32*)&sKh[n * QK_STRIDE + col];
                u32 kh1 = *(u32*)&sKh[n * QK_STRIDE + col + 8];
                u32 kl0 = *(u32*)&sKl[n * QK_STRIDE + col];
                u32 kl1 = *(u32*)&sKl[n * QK_STRIDE + col + 8];
                mma16816(s[j], qh0, qh1, qh2, qh3, kh0, kh1);
                mma16816(s[j], qh0, qh1, qh2, qh3, kl0, kl1);
                mma16816(s[j], ql0, ql1, ql2, ql3, kh0, kh1);
            }
        }

        // ---- scale + mask ----
#pragma unroll
        for (int j = 0; j < 16; j++) {
            float mk0 = maskS[j * 8 + 2 * c];
            float mk1 = maskS[j * 8 + 2 * c + 1];
            s[j][0] = s[j][0] * 0.125f + mk0;
            s[j][1] = s[j][1] * 0.125f + mk1;
            s[j][2] = s[j][2] * 0.125f + mk0;
            s[j][3] = s[j][3] * 0.125f + mk1;
        }

        // ---- online softmax ----
        float mt0 = -1e30f, mt1 = -1e30f;
#pragma unroll
        for (int j = 0; j < 16; j++) {
            mt0 = fmaxf(mt0, fmaxf(s[j][0], s[j][1]));
            mt1 = fmaxf(mt1, fmaxf(s[j][2], s[j][3]));
        }
        mt0 = fmaxf(mt0, __shfl_xor_sync(0xffffffffu, mt0, 1));
        mt0 = fmaxf(mt0, __shfl_xor_sync(0xffffffffu, mt0, 2));
        mt1 = fmaxf(mt1, __shfl_xor_sync(0xffffffffu, mt1, 1));
        mt1 = fmaxf(mt1, __shfl_xor_sync(0xffffffffu, mt1, 2));
        float mn0 = fmaxf(m0, mt0), mn1 = fmaxf(m1, mt1);
        float al0 = __expf(m0 - mn0), al1 = __expf(m1 - mn1);
        m0 = mn0; m1 = mn1;

        float rs0 = 0.0f, rs1 = 0.0f;
#pragma unroll
        for (int j = 0; j < 16; j++) {
            s[j][0] = __expf(s[j][0] - mn0); rs0 += s[j][0];
            s[j][1] = __expf(s[j][1] - mn0); rs0 += s[j][1];
            s[j][2] = __expf(s[j][2] - mn1); rs1 += s[j][2];
            s[j][3] = __expf(s[j][3] - mn1); rs1 += s[j][3];
        }
        rs0 += __shfl_xor_sync(0xffffffffu, rs0, 1);
        rs0 += __shfl_xor_sync(0xffffffffu, rs0, 2);
        rs1 += __shfl_xor_sync(0xffffffffu, rs1, 1);
        rs1 += __shfl_xor_sync(0xffffffffu, rs1, 2);
        l0 = l0 * al0 + rs0;
        l1 = l1 * al1 + rs1;
#pragma unroll
        for (int j = 0; j < 8; j++) {
            o[j][0] *= al0; o[j][1] *= al0;
            o[j][2] *= al1; o[j][3] *= al1;
        }

        // ---- O += P V (split; P regs -> A frags directly) ----
#pragma unroll
        for (int kk = 0; kk < 8; kk++) {
            u32 pa0, pa1, pa2, pa3, pb0, pb1, pb2, pb3;
            split_pair(s[2 * kk][0], s[2 * kk][1], pa0, pb0);
            split_pair(s[2 * kk][2], s[2 * kk][3], pa1, pb1);
            split_pair(s[2 * kk + 1][0], s[2 * kk + 1][1], pa2, pb2);
            split_pair(s[2 * kk + 1][2], s[2 * kk + 1][3], pa3, pb3);
            const int col = kk * 16 + 2 * c;
#pragma unroll
            for (int j = 0; j < 8; j++) {
                int n = j * 8 + g;
                u32 vh0 = *(u32*)&sVh[n * V_STRIDE + col];
                u32 vh1 = *(u32*)&sVh[n * V_STRIDE + col + 8];
                u32 vl0 = *(u32*)&sVl[n * V_STRIDE + col];
                u32 vl1 = *(u32*)&sVl[n * V_STRIDE + col + 8];
                mma16816(o[j], pa0, pa1, pa2, pa3, vh0, vh1);
                mma16816(o[j], pa0, pa1, pa2, pa3, vl0, vl1);
                mma16816(o[j], pb0, pb1, pb2, pb3, vh0, vh1);
            }
        }
    }

    // ---- epilogue: (O / l) * eff_gate -> hi/lo bf16 at [b][s][h*64+d] ----
    float gv = gate[h];
    float eff = (gv >= GATE_EPS) ? gv : 0.0f;
    float inv0 = eff / l0, inv1 = eff / l1;
    int row0 = bm + mr + g;
#pragma unroll
    for (int j = 0; j < 8; j++) {
        int e0 = h * 64 + j * 8 + 2 * c;
        size_t base0 = ((size_t)b * SEQ + row0) * 1024 + e0;
        size_t base1 = ((size_t)b * SEQ + row0 + 8) * 1024 + e0;
        u32 hp, lp;
        split_pair(o[j][0] * inv0, o[j][1] * inv0, hp, lp);
        *(u32*)&g_Ch[base0] = hp;
        *(u32*)&g_Cl[base0] = lp;
        split_pair(o[j][2] * inv1, o[j][3] * inv1, hp, lp);
        *(u32*)&g_Ch[base1] = hp;
        *(u32*)&g_Cl[base1] = lp;
    }
}

// ================================================================================
// O-projection GEMM (split-bf16 mma): out[m][n] = scale * sum_k C[m][k] WoT[n][k]
// ================================================================================
__global__ __launch_bounds__(256) void oproj_gemm_kernel(const float* __restrict__ gate,
                                                         float* __restrict__ out) {
    __shared__ __nv_bfloat16 Ah[128][40], Al[128][40], Bh[128][40], Bl[128][40];

    const int bm = blockIdx.x * 128;
    const int bn = blockIdx.y * 128;

    const __nv_bfloat16* __restrict__ pAh = g_Ch;
    const __nv_bfloat16* __restrict__ pAl = g_Cl;
    const __nv_bfloat16* __restrict__ pBh = g_Wh + 3u * 1048576;
    const __nv_bfloat16* __restrict__ pBl = g_Wl + 3u * 1048576;

    const int tid = threadIdx.x;
    const int lane = tid & 31, warp = tid >> 5;
    const int wr = warp & 3, wc = warp >> 2;
    const int g = lane >> 2, c = lane & 3;

    float acc[2][8][4];
#pragma unroll
    for (int mt = 0; mt < 2; mt++)
#pragma unroll
        for (int j = 0; j < 8; j++)
#pragma unroll
            for (int q = 0; q < 4; q++) acc[mt][j][q] = 0.0f;

    for (int k0 = 0; k0 < 1024; k0 += 32) {
#pragma unroll
        for (int i = 0; i < 2; i++) {
            int idx = tid * 2 + i;
            int row = idx >> 2, seg = idx & 3;
            *(uint4*)&Ah[row][seg * 8] = *(const uint4*)&pAh[(size_t)(bm + row) * 1024 + k0 + seg * 8];
            *(uint4*)&Al[row][seg * 8] = *(const uint4*)&pAl[(size_t)(bm + row) * 1024 + k0 + seg * 8];
            *(uint4*)&Bh[row][seg * 8] = *(const uint4*)&pBh[(size_t)(bn + row) * 1024 + k0 + seg * 8];
            *(uint4*)&Bl[row][seg * 8] = *(const uint4*)&pBl[(size_t)(bn + row) * 1024 + k0 + seg * 8];
        }
        __syncthreads();
#pragma unroll
        for (int kk = 0; kk < 2; kk++) {
            const int col = kk * 16 + 2 * c;
            u32 ah[2][4], al[2][4];
#pragma unroll
            for (int mt = 0; mt < 2; mt++) {
                int r = wr * 32 + mt * 16 + g;
                ah[mt][0] = *(u32*)&Ah[r][col];
                ah[mt][1] = *(u32*)&Ah[r + 8][col];
                ah[mt][2] = *(u32*)&Ah[r][col + 8];
                ah[mt][3] = *(u32*)&Ah[r + 8][col + 8];
                al[mt][0] = *(u32*)&Al[r][col];
                al[mt][1] = *(u32*)&Al[r + 8][col];
                al[mt][2] = *(u32*)&Al[r][col + 8];
                al[mt][3] = *(u32*)&Al[r + 8][col + 8];
            }
#pragma unroll
            for (int j = 0; j < 8; j++) {
                int n = wc * 64 + j * 8 + g;
                u32 bh0 = *(u32*)&Bh[n][col], bh1 = *(u32*)&Bh[n][col + 8];
                u32 bl0 = *(u32*)&Bl[n][col], bl1 = *(u32*)&Bl[n][col + 8];
#pragma unroll
                for (int mt = 0; mt < 2; mt++) {
                    mma16816(acc[mt][j], ah[mt][0], ah[mt][1], ah[mt][2], ah[mt][3], bh0, bh1);
                    mma16816(acc[mt][j], ah[mt][0], ah[mt][1], ah[mt][2], ah[mt][3], bl0, bl1);
                    mma16816(acc[mt][j], al[mt][0], al[mt][1], al[mt][2], al[mt][3], bh0, bh1);
                }
            }
        }
        __syncthreads();
    }

    int cnt = 0;
#pragma unroll
    for (int i = 0; i < NHEAD; i++) cnt += (gate[i] > GATE_EPS) ? 1 : 0;
    float scale = (cnt > 0) ? 1.0f / fmaxf(1.0f, (float)cnt / (float)NHEAD) : 1.0f;

#pragma unroll
    for (int mt = 0; mt < 2; mt++) {
        int row = bm + wr * 32 + mt * 16 + g;
#pragma unroll
        for (int j = 0; j < 8; j++) {
            int n0 = bn + wc * 64 + j * 8 + 2 * c;
            float2 v0 = make_float2(acc[mt][j][0] * scale, acc[mt][j][1] * scale);
            float2 v1 = make_float2(acc[mt][j][2] * scale, acc[mt][j][3] * scale);
            *(float2*)&out[(size_t)row * 1024 + n0] = v0;
            *(float2*)&out[(size_t)(row + 8) * 1024 + n0] = v1;
        }
    }
}

// ================================================================================
extern "C" void kernel_launch(void* const* d_in, const int* in_sizes, int n_in,
                              void* d_out, int out_size) {
    const float* X    = (const float*)d_in[0];   // [B,S,E]
    const float* mask = (const float*)d_in[1];   // [B,1,1,S]
    const float* Wq   = (const float*)d_in[2];   // [H,E,D]
    const float* Wk   = (const float*)d_in[3];
    const float* Wv   = (const float*)d_in[4];
    const float* Wo   = (const float*)d_in[5];   // [H,D,E]
    const float* gate = (const float*)d_in[6];   // [H]
    float* out = (float*)d_out;

    cudaFuncSetAttribute(flash_kernel, cudaFuncAttributeMaxDynamicSharedMemorySize,
                         FLASH_SMEM);

    prep_x_kernel<<<16384, 256>>>(X);
    transpose_wqkv_kernel<<<dim3(2, 32, 48), dim3(32, 8)>>>(Wq, Wk, Wv);
    transpose_wo_kernel<<<dim3(32, 32), dim3(32, 8)>>>(Wo);
    qkv_gemm_kernel<<<dim3(32, 8, 3), 256>>>();
    flash_kernel<<<dim3(16, 32), 256, FLASH_SMEM>>>(mask, gate);
    oproj_gemm_kernel<<<dim3(32, 8), 256>>>(gate, out);
}

// round 3
// speedup vs baseline: 3.3417x; 1.4110x over previous
#include <cuda_runtime.h>
#include <cuda_bf16.h>
#include <math.h>

#define BATCH 2
#define NHEAD 16
#define SEQ   2048
#define EMB   1024
#define HDIM  64
#define GATE_EPS 1e-4f

typedef unsigned int u32;

// ------------------ scratch (bf16 hi/lo splits) ------------------
__device__ __nv_bfloat16 g_Xh[4096 * 1024];
__device__ __nv_bfloat16 g_Xl[4096 * 1024];
// W: slot 0..2 = Wq/Wk/Wv transposed to [n=(h,d)][k=e]; slot 3 = Wo^T [n=e][k=(h,d)]
__device__ __nv_bfloat16 g_Wh[4 * 1024 * 1024];
__device__ __nv_bfloat16 g_Wl[4 * 1024 * 1024];
// Q,K: [b*16+h][s][d] bf16 hi/lo
__device__ __nv_bfloat16 g_Qh[32 * 2048 * 64];
__device__ __nv_bfloat16 g_Ql[32 * 2048 * 64];
__device__ __nv_bfloat16 g_Kh[32 * 2048 * 64];
__device__ __nv_bfloat16 g_Kl[32 * 2048 * 64];
// V TRANSPOSED: [b*16+h][d][s]  (so flash can cp.async straight rows)
__device__ __nv_bfloat16 g_Vh[32 * 64 * 2048];
__device__ __nv_bfloat16 g_Vl[32 * 64 * 2048];
// context: [b][s][h*64+d] bf16 hi/lo
__device__ __nv_bfloat16 g_Ch[4096 * 1024];
__device__ __nv_bfloat16 g_Cl[4096 * 1024];

// ------------------------------- helpers ---------------------------------------
__device__ __forceinline__ void split_pair(float x, float y, u32 &hi, u32 &lo) {
    __nv_bfloat16 hx = __float2bfloat16(x);
    __nv_bfloat16 hy = __float2bfloat16(y);
    __nv_bfloat16 lx = __float2bfloat16(x - __bfloat162float(hx));
    __nv_bfloat16 ly = __float2bfloat16(y - __bfloat162float(hy));
    __nv_bfloat162 hp = __halves2bfloat162(hx, hy);
    __nv_bfloat162 lp = __halves2bfloat162(lx, ly);
    hi = *reinterpret_cast<u32*>(&hp);
    lo = *reinterpret_cast<u32*>(&lp);
}

__device__ __forceinline__ void split1(float x, __nv_bfloat16 &h, __nv_bfloat16 &l) {
    h = __float2bfloat16(x);
    l = __float2bfloat16(x - __bfloat162float(h));
}

__device__ __forceinline__ void mma16816(float* d, u32 a0, u32 a1, u32 a2, u32 a3,
                                         u32 b0, u32 b1) {
    asm volatile(
        "mma.sync.aligned.m16n8k16.row.col.f32.bf16.bf16.f32 "
        "{%0,%1,%2,%3}, {%4,%5,%6,%7}, {%8,%9}, {%0,%1,%2,%3};\n"
        : "+f"(d[0]), "+f"(d[1]), "+f"(d[2]), "+f"(d[3])
        : "r"(a0), "r"(a1), "r"(a2), "r"(a3), "r"(b0), "r"(b1));
}

__device__ __forceinline__ void cp16(void* dst, const void* src) {
    u32 d = (u32)__cvta_generic_to_shared(dst);
    asm volatile("cp.async.cg.shared.global [%0], [%1], 16;\n" :: "r"(d), "l"(src));
}
__device__ __forceinline__ void cp_commit() { asm volatile("cp.async.commit_group;\n"); }
__device__ __forceinline__ void cp_wait1()  { asm volatile("cp.async.wait_group 1;\n"); }
__device__ __forceinline__ void cp_wait0()  { asm volatile("cp.async.wait_group 0;\n"); }

// ================================================================================
// prep_x: split hidden_states fp32 -> hi/lo bf16
// ================================================================================
__global__ __launch_bounds__(256) void prep_x_kernel(const float* __restrict__ X) {
    int idx = blockIdx.x * 256 + threadIdx.x;
    float x = X[idx];
    __nv_bfloat16 h = __float2bfloat16(x);
    g_Xh[idx] = h;
    g_Xl[idx] = __float2bfloat16(x - __bfloat162float(h));
}

// ================================================================================
// transpose W_q/W_k/W_v: per head, [E][D] -> [D][E]
// ================================================================================
__global__ void transpose_wqkv_kernel(const float* __restrict__ Wq,
                                      const float* __restrict__ Wk,
                                      const float* __restrict__ Wv) {
    __shared__ float tile[32][33];
    int z = blockIdx.z;
    int w = z >> 4, h = z & 15;
    const float* in = ((w == 0) ? Wq : (w == 1) ? Wk : Wv) + (size_t)h * EMB * HDIM;
    __nv_bfloat16* oh = g_Wh + (size_t)w * 1048576 + (size_t)h * 64 * 1024;
    __nv_bfloat16* ol = g_Wl + (size_t)w * 1048576 + (size_t)h * 64 * 1024;
    int e0 = blockIdx.y * 32, d0 = blockIdx.x * 32;
    for (int i = threadIdx.y; i < 32; i += 8)
        tile[i][threadIdx.x] = in[(size_t)(e0 + i) * HDIM + d0 + threadIdx.x];
    __syncthreads();
    for (int i = threadIdx.y; i < 32; i += 8) {
        float v = tile[threadIdx.x][i];
        __nv_bfloat16 hh = __float2bfloat16(v);
        oh[(size_t)(d0 + i) * 1024 + e0 + threadIdx.x] = hh;
        ol[(size_t)(d0 + i) * 1024 + e0 + threadIdx.x] =
            __float2bfloat16(v - __bfloat162float(hh));
    }
}

// ================================================================================
// transpose W_o: [1024(k)][1024(n)] -> [n][k] into slot 3
// ================================================================================
__global__ void transpose_wo_kernel(const float* __restrict__ Wo) {
    __shared__ float tile[32][33];
    __nv_bfloat16* oh = g_Wh + 3u * 1048576;
    __nv_bfloat16* ol = g_Wl + 3u * 1048576;
    int k0 = blockIdx.y * 32, n0 = blockIdx.x * 32;
    for (int i = threadIdx.y; i < 32; i += 8)
        tile[i][threadIdx.x] = Wo[(size_t)(k0 + i) * 1024 + n0 + threadIdx.x];
    __syncthreads();
    for (int i = threadIdx.y; i < 32; i += 8) {
        float v = tile[threadIdx.x][i];
        __nv_bfloat16 hh = __float2bfloat16(v);
        oh[(size_t)(n0 + i) * 1024 + k0 + threadIdx.x] = hh;
        ol[(size_t)(n0 + i) * 1024 + k0 + threadIdx.x] =
            __float2bfloat16(v - __bfloat162float(hh));
    }
}

// ================================================================================
// QKV GEMM: M=4096, N=1024, K=1024; z selects Q/K/V.  2-stage cp.async pipeline,
// 2 CTAs/SM.  Dynamic smem: per stage {Ah,Al,Bh,Bl}[128][40] -> 80 KB total.
// ================================================================================
#define GEMM_SMEM 81920
#define ST_STRIDE 20480   // elems per stage
#define OFF_AL 5120
#define OFF_BH 10240
#define OFF_BL 15360

__global__ __launch_bounds__(256, 2) void qkv_gemm_kernel() {
    extern __shared__ __nv_bfloat16 sm[];

    const int bm = blockIdx.x * 128;
    const int bn = blockIdx.y * 128;
    const int z  = blockIdx.z;

    const __nv_bfloat16* __restrict__ pAh = g_Xh;
    const __nv_bfloat16* __restrict__ pAl = g_Xl;
    const __nv_bfloat16* __restrict__ pBh = g_Wh + (size_t)z * 1048576;
    const __nv_bfloat16* __restrict__ pBl = g_Wl + (size_t)z * 1048576;

    const int tid = threadIdx.x;
    const int lane = tid & 31, warp = tid >> 5;
    const int wr = warp & 3, wc = warp >> 2;
    const int g = lane >> 2, c = lane & 3;

    const int lrow = tid >> 1;                 // 0..127
    const int lseg0 = (tid & 1) * 2;           // 0 or 2

    float acc[2][8][4];
#pragma unroll
    for (int mt = 0; mt < 2; mt++)
#pragma unroll
        for (int j = 0; j < 8; j++)
#pragma unroll
            for (int q = 0; q < 4; q++) acc[mt][j][q] = 0.0f;

    // prologue: stage 0
    {
        const int k0 = 0;
#pragma unroll
        for (int i = 0; i < 2; i++) {
            int seg = lseg0 + i;
            int off = lrow * 40 + seg * 8;
            size_t asrc = (size_t)(bm + lrow) * 1024 + k0 + seg * 8;
            size_t bsrc = (size_t)(bn + lrow) * 1024 + k0 + seg * 8;
            cp16(sm + off, pAh + asrc);
            cp16(sm + OFF_AL + off, pAl + asrc);
            cp16(sm + OFF_BH + off, pBh + bsrc);
            cp16(sm + OFF_BL + off, pBl + bsrc);
        }
        cp_commit();
    }

    for (int it = 0; it < 32; it++) {
        const int cur = it & 1;
        if (it + 1 < 32) {
            const int k0 = (it + 1) * 32;
            __nv_bfloat16* base = sm + (cur ^ 1) * ST_STRIDE;
#pragma unroll
            for (int i = 0; i < 2; i++) {
                int seg = lseg0 + i;
                int off = lrow * 40 + seg * 8;
                size_t asrc = (size_t)(bm + lrow) * 1024 + k0 + seg * 8;
                size_t bsrc = (size_t)(bn + lrow) * 1024 + k0 + seg * 8;
                cp16(base + off, pAh + asrc);
                cp16(base + OFF_AL + off, pAl + asrc);
                cp16(base + OFF_BH + off, pBh + bsrc);
                cp16(base + OFF_BL + off, pBl + bsrc);
            }
            cp_commit();
            cp_wait1();
        } else {
            cp_wait0();
        }
        __syncthreads();

        const __nv_bfloat16* Ah = sm + cur * ST_STRIDE;
        const __nv_bfloat16* Al = Ah + OFF_AL;
        const __nv_bfloat16* Bh = Ah + OFF_BH;
        const __nv_bfloat16* Bl = Ah + OFF_BL;

#pragma unroll
        for (int kk = 0; kk < 2; kk++) {
            const int col = kk * 16 + 2 * c;
            u32 ah[2][4], al[2][4];
#pragma unroll
            for (int mt = 0; mt < 2; mt++) {
                int r = wr * 32 + mt * 16 + g;
                ah[mt][0] = *(const u32*)&Ah[r * 40 + col];
                ah[mt][1] = *(const u32*)&Ah[(r + 8) * 40 + col];
                ah[mt][2] = *(const u32*)&Ah[r * 40 + col + 8];
                ah[mt][3] = *(const u32*)&Ah[(r + 8) * 40 + col + 8];
                al[mt][0] = *(const u32*)&Al[r * 40 + col];
                al[mt][1] = *(const u32*)&Al[(r + 8) * 40 + col];
                al[mt][2] = *(const u32*)&Al[r * 40 + col + 8];
                al[mt][3] = *(const u32*)&Al[(r + 8) * 40 + col + 8];
            }
#pragma unroll
            for (int j = 0; j < 8; j++) {
                int n = wc * 64 + j * 8 + g;
                u32 bh0 = *(const u32*)&Bh[n * 40 + col];
                u32 bh1 = *(const u32*)&Bh[n * 40 + col + 8];
                u32 bl0 = *(const u32*)&Bl[n * 40 + col];
                u32 bl1 = *(const u32*)&Bl[n * 40 + col + 8];
#pragma unroll
                for (int mt = 0; mt < 2; mt++) {
                    mma16816(acc[mt][j], ah[mt][0], ah[mt][1], ah[mt][2], ah[mt][3], bh0, bh1);
                    mma16816(acc[mt][j], ah[mt][0], ah[mt][1], ah[mt][2], ah[mt][3], bl0, bl1);
                    mma16816(acc[mt][j], al[mt][0], al[mt][1], al[mt][2], al[mt][3], bh0, bh1);
                }
            }
        }
        __syncthreads();
    }

    if (z == 2) {
        // V epilogue: transposed store [bh][d][s]
#pragma unroll
        for (int mt = 0; mt < 2; mt++) {
            int row = bm + wr * 32 + mt * 16 + g;
            int b = row >> 11, s = row & (SEQ - 1);
#pragma unroll
            for (int j = 0; j < 8; j++) {
                int n0 = bn + wc * 64 + j * 8 + 2 * c;
                int h = n0 >> 6, d = n0 & 63;
                size_t vb = (size_t)(b * 16 + h) * 64;
                __nv_bfloat16 vh, vl;
                split1(acc[mt][j][0], vh, vl);
                g_Vh[(vb + d) * 2048 + s] = vh;  g_Vl[(vb + d) * 2048 + s] = vl;
                split1(acc[mt][j][1], vh, vl);
                g_Vh[(vb + d + 1) * 2048 + s] = vh;  g_Vl[(vb + d + 1) * 2048 + s] = vl;
                split1(acc[mt][j][2], vh, vl);
                g_Vh[(vb + d) * 2048 + s + 8] = vh;  g_Vl[(vb + d) * 2048 + s + 8] = vl;
                split1(acc[mt][j][3], vh, vl);
                g_Vh[(vb + d + 1) * 2048 + s + 8] = vh;  g_Vl[(vb + d + 1) * 2048 + s + 8] = vl;
            }
        }
    } else {
        __nv_bfloat16* outh = (z == 0) ? g_Qh : g_Kh;
        __nv_bfloat16* outl = (z == 0) ? g_Ql : g_Kl;
#pragma unroll
        for (int mt = 0; mt < 2; mt++) {
            int row = bm + wr * 32 + mt * 16 + g;
            int b = row >> 11, s = row & (SEQ - 1);
#pragma unroll
            for (int j = 0; j < 8; j++) {
                int n0 = bn + wc * 64 + j * 8 + 2 * c;
                int h = n0 >> 6, d = n0 & 63;
                size_t base = (((size_t)(b * 16 + h)) * SEQ + s) * 64 + d;
                u32 hp, lp;
                split_pair(acc[mt][j][0], acc[mt][j][1], hp, lp);
                *(u32*)&outh[base] = hp;
                *(u32*)&outl[base] = lp;
                size_t base8 = base + 8 * 64;
                split_pair(acc[mt][j][2], acc[mt][j][3], hp, lp);
                *(u32*)&outh[base8] = hp;
                *(u32*)&outl[base8] = lp;
            }
        }
    }
}

// ================================================================================
// Fused flash attention, 2-stage cp.async pipeline on K/V/mask.
// smem elems: Qh 0, Ql 9216, Kh 18432+st*9216, Kl 36864+st*9216,
//             Vh 55296+st*8704, Vl 72704+st*8704; mask floats at byte 180224.
// ================================================================================
#define QK_STRIDE 72
#define V_STRIDE  136
#define F_QH 0
#define F_QL 9216
#define F_KH 18432
#define F_KL 36864
#define F_VH 55296
#define F_VL 72704
#define FLASH_SMEM 181248

__global__ __launch_bounds__(256, 1) void flash_kernel(const float* __restrict__ mask,
                                                       const float* __restrict__ gate) {
    extern __shared__ char smraw[];
    __nv_bfloat16* S = (__nv_bfloat16*)smraw;
    float* maskS = (float*)(smraw + 180224);

    const int bm = blockIdx.x * 128;
    const int bh = blockIdx.y;
    const int b = bh >> 4, h = bh & 15;

    const int tid = threadIdx.x;
    const int lane = tid & 31, warp = tid >> 5;
    const int g = lane >> 2, c = lane & 3;
    const int mr = warp * 16;

    // prologue: Q + stage 0 K/V/mask
    {
        const size_t qbase = ((size_t)bh * SEQ + bm) * 64;
#pragma unroll
        for (int i = 0; i < 4; i++) {
            int idx = tid + i * 256;
            int row = idx >> 3, seg = idx & 7;
            cp16(S + F_QH + row * QK_STRIDE + seg * 8, g_Qh + qbase + (size_t)row * 64 + seg * 8);
            cp16(S + F_QL + row * QK_STRIDE + seg * 8, g_Ql + qbase + (size_t)row * 64 + seg * 8);
        }
        const size_t kbase = (size_t)bh * SEQ * 64;
#pragma unroll
        for (int i = 0; i < 4; i++) {
            int idx = tid + i * 256;
            int row = idx >> 3, seg = idx & 7;
            cp16(S + F_KH + row * QK_STRIDE + seg * 8, g_Kh + kbase + (size_t)row * 64 + seg * 8);
            cp16(S + F_KL + row * QK_STRIDE + seg * 8, g_Kl + kbase + (size_t)row * 64 + seg * 8);
        }
        const size_t vbase = (size_t)bh * 64 * 2048;
#pragma unroll
        for (int i = 0; i < 4; i++) {
            int idx = tid + i * 256;
            int d = idx >> 4, seg = idx & 15;
            cp16(S + F_VH + d * V_STRIDE + seg * 8, g_Vh + vbase + (size_t)d * 2048 + seg * 8);
            cp16(S + F_VL + d * V_STRIDE + seg * 8, g_Vl + vbase + (size_t)d * 2048 + seg * 8);
        }
        if (tid < 32) cp16(maskS + tid * 4, mask + b * SEQ + tid * 4);
        cp_commit();
    }

    float o[8][4];
#pragma unroll
    for (int j = 0; j < 8; j++)
#pragma unroll
        for (int q = 0; q < 4; q++) o[j][q] = 0.0f;
    float m0 = -1e30f, m1 = -1e30f, l0 = 0.0f, l1 = 0.0f;

    for (int it = 0; it < 16; it++) {
        const int cur = it & 1;
        if (it + 1 < 16) {
            const int st = cur ^ 1;
            const int t0 = (it + 1) * 128;
            const size_t kbase = ((size_t)bh * SEQ + t0) * 64;
#pragma unroll
            for (int i = 0; i < 4; i++) {
                int idx = tid + i * 256;
                int row = idx >> 3, seg = idx & 7;
                cp16(S + F_KH + st * 9216 + row * QK_STRIDE + seg * 8,
                     g_Kh + kbase + (size_t)row * 64 + seg * 8);
                cp16(S + F_KL + st * 9216 + row * QK_STRIDE + seg * 8,
                     g_Kl + kbase + (size_t)row * 64 + seg * 8);
            }
            const size_t vbase = (size_t)bh * 64 * 2048 + t0;
#pragma unroll
            for (int i = 0; i < 4; i++) {
                int idx = tid + i * 256;
                int d = idx >> 4, seg = idx & 15;
                cp16(S + F_VH + st * 8704 + d * V_STRIDE + seg * 8,
                     g_Vh + vbase + (size_t)d * 2048 + seg * 8);
                cp16(S + F_VL + st * 8704 + d * V_STRIDE + seg * 8,
                     g_Vl + vbase + (size_t)d * 2048 + seg * 8);
            }
            if (tid < 32) cp16(maskS + st * 128 + tid * 4, mask + b * SEQ + t0 + tid * 4);
            cp_commit();
            cp_wait1();
        } else {
            cp_wait0();
        }
        __syncthreads();

        const __nv_bfloat16* sQh = S + F_QH;
        const __nv_bfloat16* sQl = S + F_QL;
        const __nv_bfloat16* sKh = S + F_KH + cur * 9216;
        const __nv_bfloat16* sKl = S + F_KL + cur * 9216;
        const __nv_bfloat16* sVh = S + F_VH + cur * 8704;
        const __nv_bfloat16* sVl = S + F_VL + cur * 8704;
        const float* mk = maskS + cur * 128;

        // ---- S = Q K^T (split) ----
        float s[16][4];
#pragma unroll
        for (int j = 0; j < 16; j++)
#pragma unroll
            for (int q = 0; q < 4; q++) s[j][q] = 0.0f;

#pragma unroll
        for (int kk = 0; kk < 4; kk++) {
            const int col = kk * 16 + 2 * c;
            u32 qh0 = *(const u32*)&sQh[(mr + g) * QK_STRIDE + col];
            u32 qh1 = *(const u32*)&sQh[(mr + g + 8) * QK_STRIDE + col];
            u32 qh2 = *(const u32*)&sQh[(mr + g) * QK_STRIDE + col + 8];
            u32 qh3 = *(const u32*)&sQh[(mr + g + 8) * QK_STRIDE + col + 8];
            u32 ql0 = *(const u32*)&sQl[(mr + g) * QK_STRIDE + col];
            u32 ql1 = *(const u32*)&sQl[(mr + g + 8) * QK_STRIDE + col];
            u32 ql2 = *(const u32*)&sQl[(mr + g) * QK_STRIDE + col + 8];
            u32 ql3 = *(const u32*)&sQl[(mr + g + 8) * QK_STRIDE + col + 8];
#pragma unroll
            for (int j = 0; j < 16; j++) {
                int n = j * 8 + g;
                u32 kh0 = *(const u32*)&sKh[n * QK_STRIDE + col];
                u32 kh1 = *(const u32*)&sKh[n * QK_STRIDE + col + 8];
                u32 kl0 = *(const u32*)&sKl[n * QK_STRIDE + col];
                u32 kl1 = *(const u32*)&sKl[n * QK_STRIDE + col + 8];
                mma16816(s[j], qh0, qh1, qh2, qh3, kh0, kh1);
                mma16816(s[j], qh0, qh1, qh2, qh3, kl0, kl1);
                mma16816(s[j], ql0, ql1, ql2, ql3, kh0, kh1);
            }
        }

        // ---- scale + mask ----
#pragma unroll
        for (int j = 0; j < 16; j++) {
            float mk0 = mk[j * 8 + 2 * c];
            float mk1 = mk[j * 8 + 2 * c + 1];
            s[j][0] = s[j][0] * 0.125f + mk0;
            s[j][1] = s[j][1] * 0.125f + mk1;
            s[j][2] = s[j][2] * 0.125f + mk0;
            s[j][3] = s[j][3] * 0.125f + mk1;
        }

        // ---- online softmax ----
        float mt0 = -1e30f, mt1 = -1e30f;
#pragma unroll
        for (int j = 0; j < 16; j++) {
            mt0 = fmaxf(mt0, fmaxf(s[j][0], s[j][1]));
            mt1 = fmaxf(mt1, fmaxf(s[j][2], s[j][3]));
        }
        mt0 = fmaxf(mt0, __shfl_xor_sync(0xffffffffu, mt0, 1));
        mt0 = fmaxf(mt0, __shfl_xor_sync(0xffffffffu, mt0, 2));
        mt1 = fmaxf(mt1, __shfl_xor_sync(0xffffffffu, mt1, 1));
        mt1 = fmaxf(mt1, __shfl_xor_sync(0xffffffffu, mt1, 2));
        float mn0 = fmaxf(m0, mt0), mn1 = fmaxf(m1, mt1);
        float al0 = __expf(m0 - mn0), al1 = __expf(m1 - mn1);
        m0 = mn0; m1 = mn1;

        float rs0 = 0.0f, rs1 = 0.0f;
#pragma unroll
        for (int j = 0; j < 16; j++) {
            s[j][0] = __expf(s[j][0] - mn0); rs0 += s[j][0];
            s[j][1] = __expf(s[j][1] - mn0); rs0 += s[j][1];
            s[j][2] = __expf(s[j][2] - mn1); rs1 += s[j][2];
            s[j][3] = __expf(s[j][3] - mn1); rs1 += s[j][3];
        }
        rs0 += __shfl_xor_sync(0xffffffffu, rs0, 1);
        rs0 += __shfl_xor_sync(0xffffffffu, rs0, 2);
        rs1 += __shfl_xor_sync(0xffffffffu, rs1, 1);
        rs1 += __shfl_xor_sync(0xffffffffu, rs1, 2);
        l0 = l0 * al0 + rs0;
        l1 = l1 * al1 + rs1;
#pragma unroll
        for (int j = 0; j < 8; j++) {
            o[j][0] *= al0; o[j][1] *= al0;
            o[j][2] *= al1; o[j][3] *= al1;
        }

        // ---- O += P V (split) ----
#pragma unroll
        for (int kk = 0; kk < 8; kk++) {
            u32 pa0, pa1, pa2, pa3, pb0, pb1, pb2, pb3;
            split_pair(s[2 * kk][0], s[2 * kk][1], pa0, pb0);
            split_pair(s[2 * kk][2], s[2 * kk][3], pa1, pb1);
            split_pair(s[2 * kk + 1][0], s[2 * kk + 1][1], pa2, pb2);
            split_pair(s[2 * kk + 1][2], s[2 * kk + 1][3], pa3, pb3);
            const int col = kk * 16 + 2 * c;
#pragma unroll
            for (int j = 0; j < 8; j++) {
                int n = j * 8 + g;
                u32 vh0 = *(const u32*)&sVh[n * V_STRIDE + col];
                u32 vh1 = *(const u32*)&sVh[n * V_STRIDE + col + 8];
                u32 vl0 = *(const u32*)&sVl[n * V_STRIDE + col];
                u32 vl1 = *(const u32*)&sVl[n * V_STRIDE + col + 8];
                mma16816(o[j], pa0, pa1, pa2, pa3, vh0, vh1);
                mma16816(o[j], pa0, pa1, pa2, pa3, vl0, vl1);
                mma16816(o[j], pb0, pb1, pb2, pb3, vh0, vh1);
            }
        }
        __syncthreads();
    }

    // ---- epilogue ----
    float gv = gate[h];
    float eff = (gv >= GATE_EPS) ? gv : 0.0f;
    float inv0 = eff / l0, inv1 = eff / l1;
    int row0 = bm + mr + g;
#pragma unroll
    for (int j = 0; j < 8; j++) {
        int e0 = h * 64 + j * 8 + 2 * c;
        size_t base0 = ((size_t)b * SEQ + row0) * 1024 + e0;
        size_t base1 = ((size_t)b * SEQ + row0 + 8) * 1024 + e0;
        u32 hp, lp;
        split_pair(o[j][0] * inv0, o[j][1] * inv0, hp, lp);
        *(u32*)&g_Ch[base0] = hp;
        *(u32*)&g_Cl[base0] = lp;
        split_pair(o[j][2] * inv1, o[j][3] * inv1, hp, lp);
        *(u32*)&g_Ch[base1] = hp;
        *(u32*)&g_Cl[base1] = lp;
    }
}

// ================================================================================
// O-projection GEMM, same 2-stage pipeline as qkv.
// ================================================================================
__global__ __launch_bounds__(256, 2) void oproj_gemm_kernel(const float* __restrict__ gate,
                                                            float* __restrict__ out) {
    extern __shared__ __nv_bfloat16 sm[];

    const int bm = blockIdx.x * 128;
    const int bn = blockIdx.y * 128;

    const __nv_bfloat16* __restrict__ pAh = g_Ch;
    const __nv_bfloat16* __restrict__ pAl = g_Cl;
    const __nv_bfloat16* __restrict__ pBh = g_Wh + 3u * 1048576;
    const __nv_bfloat16* __restrict__ pBl = g_Wl + 3u * 1048576;

    const int tid = threadIdx.x;
    const int lane = tid & 31, warp = tid >> 5;
    const int wr = warp & 3, wc = warp >> 2;
    const int g = lane >> 2, c = lane & 3;

    const int lrow = tid >> 1;
    const int lseg0 = (tid & 1) * 2;

    float acc[2][8][4];
#pragma unroll
    for (int mt = 0; mt < 2; mt++)
#pragma unroll
        for (int j = 0; j < 8; j++)
#pragma unroll
            for (int q = 0; q < 4; q++) acc[mt][j][q] = 0.0f;

    {
#pragma unroll
        for (int i = 0; i < 2; i++) {
            int seg = lseg0 + i;
            int off = lrow * 40 + seg * 8;
            size_t asrc = (size_t)(bm + lrow) * 1024 + seg * 8;
            size_t bsrc = (size_t)(bn + lrow) * 1024 + seg * 8;
            cp16(sm + off, pAh + asrc);
            cp16(sm + OFF_AL + off, pAl + asrc);
            cp16(sm + OFF_BH + off, pBh + bsrc);
            cp16(sm + OFF_BL + off, pBl + bsrc);
        }
        cp_commit();
    }

    for (int it = 0; it < 32; it++) {
        const int cur = it & 1;
        if (it + 1 < 32) {
            const int k0 = (it + 1) * 32;
            __nv_bfloat16* base = sm + (cur ^ 1) * ST_STRIDE;
#pragma unroll
            for (int i = 0; i < 2; i++) {
                int seg = lseg0 + i;
                int off = lrow * 40 + seg * 8;
                size_t asrc = (size_t)(bm + lrow) * 1024 + k0 + seg * 8;
                size_t bsrc = (size_t)(bn + lrow) * 1024 + k0 + seg * 8;
                cp16(base + off, pAh + asrc);
                cp16(base + OFF_AL + off, pAl + asrc);
                cp16(base + OFF_BH + off, pBh + bsrc);
                cp16(base + OFF_BL + off, pBl + bsrc);
            }
            cp_commit();
            cp_wait1();
        } else {
            cp_wait0();
        }
        __syncthreads();

        const __nv_bfloat16* Ah = sm + cur * ST_STRIDE;
        const __nv_bfloat16* Al = Ah + OFF_AL;
        const __nv_bfloat16* Bh = Ah + OFF_BH;
        const __nv_bfloat16* Bl = Ah + OFF_BL;

#pragma unroll
        for (int kk = 0; kk < 2; kk++) {
            const int col = kk * 16 + 2 * c;
            u32 ah[2][4], al[2][4];
#pragma unroll
            for (int mt = 0; mt < 2; mt++) {
                int r = wr * 32 + mt * 16 + g;
                ah[mt][0] = *(const u32*)&Ah[r * 40 + col];
                ah[mt][1] = *(const u32*)&Ah[(r + 8) * 40 + col];
                ah[mt][2] = *(const u32*)&Ah[r * 40 + col + 8];
                ah[mt][3] = *(const u32*)&Ah[(r + 8) * 40 + col + 8];
                al[mt][0] = *(const u32*)&Al[r * 40 + col];
                al[mt][1] = *(const u32*)&Al[(r + 8) * 40 + col];
                al[mt][2] = *(const u32*)&Al[r * 40 + col + 8];
                al[mt][3] = *(const u32*)&Al[(r + 8) * 40 + col + 8];
            }
#pragma unroll
            for (int j = 0; j < 8; j++) {
                int n = wc * 64 + j * 8 + g;
                u32 bh0 = *(const u32*)&Bh[n * 40 + col];
                u32 bh1 = *(const u32*)&Bh[n * 40 + col + 8];
                u32 bl0 = *(const u32*)&Bl[n * 40 + col];
                u32 bl1 = *(const u32*)&Bl[n * 40 + col + 8];
#pragma unroll
                for (int mt = 0; mt < 2; mt++) {
                    mma16816(acc[mt][j], ah[mt][0], ah[mt][1], ah[mt][2], ah[mt][3], bh0, bh1);
                    mma16816(acc[mt][j], ah[mt][0], ah[mt][1], ah[mt][2], ah[mt][3], bl0, bl1);
                    mma16816(acc[mt][j], al[mt][0], al[mt][1], al[mt][2], al[mt][3], bh0, bh1);
                }
            }
        }
        __syncthreads();
    }

    int cnt = 0;
#pragma unroll
    for (int i = 0; i < NHEAD; i++) cnt += (gate[i] > GATE_EPS) ? 1 : 0;
    float scale = (cnt > 0) ? 1.0f / fmaxf(1.0f, (float)cnt / (float)NHEAD) : 1.0f;

#pragma unroll
    for (int mt = 0; mt < 2; mt++) {
        int row = bm + wr * 32 + mt * 16 + g;
#pragma unroll
        for (int j = 0; j < 8; j++) {
            int n0 = bn + wc * 64 + j * 8 + 2 * c;
            float2 v0 = make_float2(acc[mt][j][0] * scale, acc[mt][j][1] * scale);
            float2 v1 = make_float2(acc[mt][j][2] * scale, acc[mt][j][3] * scale);
            *(float2*)&out[(size_t)row * 1024 + n0] = v0;
            *(float2*)&out[(size_t)(row + 8) * 1024 + n0] = v1;
        }
    }
}

// ================================================================================
extern "C" void kernel_launch(void* const* d_in, const int* in_sizes, int n_in,
                              void* d_out, int out_size) {
    const float* X    = (const float*)d_in[0];
    const float* mask = (const float*)d_in[1];
    const float* Wq   = (const float*)d_in[2];
    const float* Wk   = (const float*)d_in[3];
    const float* Wv   = (const float*)d_in[4];
    const float* Wo   = (const float*)d_in[5];
    const float* gate = (const float*)d_in[6];
    float* out = (float*)d_out;

    cudaFuncSetAttribute(qkv_gemm_kernel, cudaFuncAttributeMaxDynamicSharedMemorySize, GEMM_SMEM);
    cudaFuncSetAttribute(oproj_gemm_kernel, cudaFuncAttributeMaxDynamicSharedMemorySize, GEMM_SMEM);
    cudaFuncSetAttribute(flash_kernel, cudaFuncAttributeMaxDynamicSharedMemorySize, FLASH_SMEM);

    prep_x_kernel<<<16384, 256>>>(X);
    transpose_wqkv_kernel<<<dim3(2, 32, 48), dim3(32, 8)>>>(Wq, Wk, Wv);
    transpose_wo_kernel<<<dim3(32, 32), dim3(32, 8)>>>(Wo);
    qkv_gemm_kernel<<<dim3(32, 8, 3), 256, GEMM_SMEM>>>();
    flash_kernel<<<dim3(16, 32), 256, FLASH_SMEM>>>(mask, gate);
    oproj_gemm_kernel<<<dim3(32, 8), 256, GEMM_SMEM>>>(gate, out);
}

// round 5
// speedup vs baseline: 3.4681x; 1.0378x over previous
#include <cuda_runtime.h>
#include <cuda_bf16.h>
#include <math.h>

#define BATCH 2
#define NHEAD 16
#define SEQ   2048
#define EMB   1024
#define HDIM  64
#define GATE_EPS 1e-4f

typedef unsigned int u32;

// ------------------ scratch (bf16 hi/lo splits) ------------------
__device__ __nv_bfloat16 g_Xh[4096 * 1024];
__device__ __nv_bfloat16 g_Xl[4096 * 1024];
// W: slot 0..2 = Wq/Wk/Wv transposed to [n=(h,d)][k=e]; slot 3 = Wo^T [n=e][k=(h,d)]
__device__ __nv_bfloat16 g_Wh[4 * 1024 * 1024];
__device__ __nv_bfloat16 g_Wl[4 * 1024 * 1024];
// Q,K: [b*16+h][s][d] bf16 hi/lo
__device__ __nv_bfloat16 g_Qh[32 * 2048 * 64];
__device__ __nv_bfloat16 g_Ql[32 * 2048 * 64];
__device__ __nv_bfloat16 g_Kh[32 * 2048 * 64];
__device__ __nv_bfloat16 g_Kl[32 * 2048 * 64];
// V TRANSPOSED: [b*16+h][d][s]
__device__ __nv_bfloat16 g_Vh[32 * 64 * 2048];
__device__ __nv_bfloat16 g_Vl[32 * 64 * 2048];
// context: [b][s][h*64+d] bf16 hi/lo
__device__ __nv_bfloat16 g_Ch[4096 * 1024];
__device__ __nv_bfloat16 g_Cl[4096 * 1024];

// ------------------------------- helpers ---------------------------------------
__device__ __forceinline__ void split_pair(float x, float y, u32 &hi, u32 &lo) {
    __nv_bfloat16 hx = __float2bfloat16(x);
    __nv_bfloat16 hy = __float2bfloat16(y);
    __nv_bfloat16 lx = __float2bfloat16(x - __bfloat162float(hx));
    __nv_bfloat16 ly = __float2bfloat16(y - __bfloat162float(hy));
    __nv_bfloat162 hp = __halves2bfloat162(hx, hy);
    __nv_bfloat162 lp = __halves2bfloat162(lx, ly);
    hi = *reinterpret_cast<u32*>(&hp);
    lo = *reinterpret_cast<u32*>(&lp);
}

__device__ __forceinline__ void split1(float x, __nv_bfloat16 &h, __nv_bfloat16 &l) {
    h = __float2bfloat16(x);
    l = __float2bfloat16(x - __bfloat162float(h));
}

__device__ __forceinline__ void mma16816(float* d, u32 a0, u32 a1, u32 a2, u32 a3,
                                         u32 b0, u32 b1) {
    asm volatile(
        "mma.sync.aligned.m16n8k16.row.col.f32.bf16.bf16.f32 "
        "{%0,%1,%2,%3}, {%4,%5,%6,%7}, {%8,%9}, {%0,%1,%2,%3};\n"
        : "+f"(d[0]), "+f"(d[1]), "+f"(d[2]), "+f"(d[3])
        : "r"(a0), "r"(a1), "r"(a2), "r"(a3), "r"(b0), "r"(b1));
}

__device__ __forceinline__ void ldsm4(u32* r, u32 saddr) {
    asm volatile(
        "ldmatrix.sync.aligned.m8n8.x4.shared.b16 {%0,%1,%2,%3}, [%4];"
        : "=r"(r[0]), "=r"(r[1]), "=r"(r[2]), "=r"(r[3]) : "r"(saddr));
}

__device__ __forceinline__ u32 smem_u32(const void* p) {
    return (u32)__cvta_generic_to_shared(p);
}

__device__ __forceinline__ void cp16(void* dst, const void* src) {
    u32 d = (u32)__cvta_generic_to_shared(dst);
    asm volatile("cp.async.cg.shared.global [%0], [%1], 16;\n" :: "r"(d), "l"(src));
}
__device__ __forceinline__ void cp_commit() { asm volatile("cp.async.commit_group;\n"); }
__device__ __forceinline__ void cp_wait1()  { asm volatile("cp.async.wait_group 1;\n"); }
__device__ __forceinline__ void cp_wait0()  { asm volatile("cp.async.wait_group 0;\n"); }

// ================================================================================
// prep_x: split hidden_states fp32 -> hi/lo bf16
// ================================================================================
__global__ __launch_bounds__(256) void prep_x_kernel(const float* __restrict__ X) {
    int idx = blockIdx.x * 256 + threadIdx.x;
    float x = X[idx];
    __nv_bfloat16 h = __float2bfloat16(x);
    g_Xh[idx] = h;
    g_Xl[idx] = __float2bfloat16(x - __bfloat162float(h));
}

// ================================================================================
// transpose W_q/W_k/W_v: per head, [E][D] -> [D][E]
// ================================================================================
__global__ void transpose_wqkv_kernel(const float* __restrict__ Wq,
                                      const float* __restrict__ Wk,
                                      const float* __restrict__ Wv) {
    __shared__ float tile[32][33];
    int z = blockIdx.z;
    int w = z >> 4, h = z & 15;
    const float* in = ((w == 0) ? Wq : (w == 1) ? Wk : Wv) + (size_t)h * EMB * HDIM;
    __nv_bfloat16* oh = g_Wh + (size_t)w * 1048576 + (size_t)h * 64 * 1024;
    __nv_bfloat16* ol = g_Wl + (size_t)w * 1048576 + (size_t)h * 64 * 1024;
    int e0 = blockIdx.y * 32, d0 = blockIdx.x * 32;
    for (int i = threadIdx.y; i < 32; i += 8)
        tile[i][threadIdx.x] = in[(size_t)(e0 + i) * HDIM + d0 + threadIdx.x];
    __syncthreads();
    for (int i = threadIdx.y; i < 32; i += 8) {
        float v = tile[threadIdx.x][i];
        __nv_bfloat16 hh = __float2bfloat16(v);
        oh[(size_t)(d0 + i) * 1024 + e0 + threadIdx.x] = hh;
        ol[(size_t)(d0 + i) * 1024 + e0 + threadIdx.x] =
            __float2bfloat16(v - __bfloat162float(hh));
    }
}

// ================================================================================
// transpose W_o: [1024(k)][1024(n)] -> [n][k] into slot 3
// ================================================================================
__global__ void transpose_wo_kernel(const float* __restrict__ Wo) {
    __shared__ float tile[32][33];
    __nv_bfloat16* oh = g_Wh + 3u * 1048576;
    __nv_bfloat16* ol = g_Wl + 3u * 1048576;
    int k0 = blockIdx.y * 32, n0 = blockIdx.x * 32;
    for (int i = threadIdx.y; i < 32; i += 8)
        tile[i][threadIdx.x] = Wo[(size_t)(k0 + i) * 1024 + n0 + threadIdx.x];
    __syncthreads();
    for (int i = threadIdx.y; i < 32; i += 8) {
        float v = tile[threadIdx.x][i];
        __nv_bfloat16 hh = __float2bfloat16(v);
        oh[(size_t)(n0 + i) * 1024 + k0 + threadIdx.x] = hh;
        ol[(size_t)(n0 + i) * 1024 + k0 + threadIdx.x] =
            __float2bfloat16(v - __bfloat162float(hh));
    }
}

// ================================================================================
// Split-bf16 GEMM with ldmatrix fragment loads.  M=4096, N=1024, K=1024.
// z selects Q/K/V (mode<3) or O-proj (mode 3).  2-stage cp.async, 2 CTAs/SM.
// smem per stage (elems): Ah@0  Al@5120  Bh@10240  Bl@15360, stride 40/row.
// ================================================================================
#define GEMM_SMEM 81920
#define ST_STRIDE 20480
#define ST_BYTES  40960

__global__ __launch_bounds__(256, 2) void gemm_kernel(int mode,
                                                      const float* __restrict__ gate,
                                                      float* __restrict__ out) {
    extern __shared__ __nv_bfloat16 sm[];
    if (mode < 0) mode = blockIdx.z;   // qkv launch passes -1

    const int bm = blockIdx.x * 128;
    const int bn = blockIdx.y * 128;

    const __nv_bfloat16 *pAh, *pAl, *pBh, *pBl;
    if (mode < 3) {
        pAh = g_Xh; pAl = g_Xl;
        pBh = g_Wh + (size_t)mode * 1048576;
        pBl = g_Wl + (size_t)mode * 1048576;
    } else {
        pAh = g_Ch; pAl = g_Cl;
        pBh = g_Wh + 3u * 1048576;
        pBl = g_Wl + 3u * 1048576;
    }

    const int tid = threadIdx.x;
    const int lane = tid & 31, warp = tid >> 5;
    const int wr = warp & 3, wc = warp >> 2;
    const int g = lane >> 2, c = lane & 3;

    const int lrow = tid >> 1;
    const int lseg0 = (tid & 1) * 2;

    // ldmatrix per-lane addresses (byte offsets into a stage buffer)
    const u32 smb = smem_u32(sm);
    const int lrA = lane & 15, lcA = (lane >> 4) << 3;
    const int lrB = (lane & 7) | ((lane >> 4) << 3);
    const int lcB = ((lane >> 3) & 1) << 3;
    const u32 offA = smb + (u32)(((wr * 32 + lrA) * 40 + lcA) * 2);
    const u32 offB = smb + 20480u + (u32)(((wc * 64 + lrB) * 40 + lcB) * 2);

    float acc[2][8][4];
#pragma unroll
    for (int mt = 0; mt < 2; mt++)
#pragma unroll
        for (int j = 0; j < 8; j++)
#pragma unroll
            for (int q = 0; q < 4; q++) acc[mt][j][q] = 0.0f;

    // prologue: stage 0
    {
#pragma unroll
        for (int i = 0; i < 2; i++) {
            int seg = lseg0 + i;
            int off = lrow * 40 + seg * 8;
            size_t asrc = (size_t)(bm + lrow) * 1024 + seg * 8;
            size_t bsrc = (size_t)(bn + lrow) * 1024 + seg * 8;
            cp16(sm + off, pAh + asrc);
            cp16(sm + 5120 + off, pAl + asrc);
            cp16(sm + 10240 + off, pBh + bsrc);
            cp16(sm + 15360 + off, pBl + bsrc);
        }
        cp_commit();
    }

    for (int it = 0; it < 32; it++) {
        const int cur = it & 1;
        if (it + 1 < 32) {
            const int k0 = (it + 1) * 32;
            __nv_bfloat16* base = sm + (cur ^ 1) * ST_STRIDE;
#pragma unroll
            for (int i = 0; i < 2; i++) {
                int seg = lseg0 + i;
                int off = lrow * 40 + seg * 8;
                size_t asrc = (size_t)(bm + lrow) * 1024 + k0 + seg * 8;
                size_t bsrc = (size_t)(bn + lrow) * 1024 + k0 + seg * 8;
                cp16(base + off, pAh + asrc);
                cp16(base + 5120 + off, pAl + asrc);
                cp16(base + 10240 + off, pBh + bsrc);
                cp16(base + 15360 + off, pBl + bsrc);
            }
            cp_commit();
            cp_wait1();
        } else {
            cp_wait0();
        }
        __syncthreads();

        const u32 stb = (u32)(cur * ST_BYTES);
#pragma unroll
        for (int kk = 0; kk < 2; kk++) {
            u32 aH[2][4], aL[2][4];
#pragma unroll
            for (int mt = 0; mt < 2; mt++) {
                ldsm4(aH[mt], offA + stb + mt * 1280 + kk * 32);
                ldsm4(aL[mt], offA + stb + 10240 + mt * 1280 + kk * 32);
            }
#pragma unroll
            for (int jj = 0; jj < 4; jj++) {
                u32 bH[4], bL[4];
                ldsm4(bH, offB + stb + jj * 1280 + kk * 32);
                ldsm4(bL, offB + stb + 10240 + jj * 1280 + kk * 32);
#pragma unroll
                for (int mt = 0; mt < 2; mt++) {
                    float* a0 = acc[mt][2 * jj];
                    float* a1 = acc[mt][2 * jj + 1];
                    mma16816(a0, aH[mt][0], aH[mt][1], aH[mt][2], aH[mt][3], bH[0], bH[1]);
                    mma16816(a0, aH[mt][0], aH[mt][1], aH[mt][2], aH[mt][3], bL[0], bL[1]);
                    mma16816(a0, aL[mt][0], aL[mt][1], aL[mt][2], aL[mt][3], bH[0], bH[1]);
                    mma16816(a1, aH[mt][0], aH[mt][1], aH[mt][2], aH[mt][3], bH[2], bH[3]);
                    mma16816(a1, aH[mt][0], aH[mt][1], aH[mt][2], aH[mt][3], bL[2], bL[3]);
                    mma16816(a1, aL[mt][0], aL[mt][1], aL[mt][2], aL[mt][3], bH[2], bH[3]);
                }
            }
        }
        __syncthreads();
    }

    // ---------------- epilogues ----------------
    if (mode == 3) {
        int cnt = 0;
#pragma unroll
        for (int i = 0; i < NHEAD; i++) cnt += (gate[i] > GATE_EPS) ? 1 : 0;
        float scale = (cnt > 0) ? 1.0f / fmaxf(1.0f, (float)cnt / (float)NHEAD) : 1.0f;
#pragma unroll
        for (int mt = 0; mt < 2; mt++) {
            int row = bm + wr * 32 + mt * 16 + g;
#pragma unroll
            for (int j = 0; j < 8; j++) {
                int n0 = bn + wc * 64 + j * 8 + 2 * c;
                float2 v0 = make_float2(acc[mt][j][0] * scale, acc[mt][j][1] * scale);
                float2 v1 = make_float2(acc[mt][j][2] * scale, acc[mt][j][3] * scale);
                *(float2*)&out[(size_t)row * 1024 + n0] = v0;
                *(float2*)&out[(size_t)(row + 8) * 1024 + n0] = v1;
            }
        }
    } else if (mode == 2) {
        // V epilogue: transposed store [bh][d][s]
#pragma unroll
        for (int mt = 0; mt < 2; mt++) {
            int row = bm + wr * 32 + mt * 16 + g;
            int b = row >> 11, s = row & (SEQ - 1);
#pragma unroll
            for (int j = 0; j < 8; j++) {
                int n0 = bn + wc * 64 + j * 8 + 2 * c;
                int h = n0 >> 6, d = n0 & 63;
                size_t vb = (size_t)(b * 16 + h) * 64;
                __nv_bfloat16 vh, vl;
                split1(acc[mt][j][0], vh, vl);
                g_Vh[(vb + d) * 2048 + s] = vh;  g_Vl[(vb + d) * 2048 + s] = vl;
                split1(acc[mt][j][1], vh, vl);
                g_Vh[(vb + d + 1) * 2048 + s] = vh;  g_Vl[(vb + d + 1) * 2048 + s] = vl;
                split1(acc[mt][j][2], vh, vl);
                g_Vh[(vb + d) * 2048 + s + 8] = vh;  g_Vl[(vb + d) * 2048 + s + 8] = vl;
                split1(acc[mt][j][3], vh, vl);
                g_Vh[(vb + d + 1) * 2048 + s + 8] = vh;  g_Vl[(vb + d + 1) * 2048 + s + 8] = vl;
            }
        }
    } else {
        __nv_bfloat16* outh = (mode == 0) ? g_Qh : g_Kh;
        __nv_bfloat16* outl = (mode == 0) ? g_Ql : g_Kl;
#pragma unroll
        for (int mt = 0; mt < 2; mt++) {
            int row = bm + wr * 32 + mt * 16 + g;
            int b = row >> 11, s = row & (SEQ - 1);
#pragma unroll
            for (int j = 0; j < 8; j++) {
                int n0 = bn + wc * 64 + j * 8 + 2 * c;
                int h = n0 >> 6, d = n0 & 63;
                size_t base = (((size_t)(b * 16 + h)) * SEQ + s) * 64 + d;
                u32 hp, lp;
                split_pair(acc[mt][j][0], acc[mt][j][1], hp, lp);
                *(u32*)&outh[base] = hp;
                *(u32*)&outl[base] = lp;
                size_t base8 = base + 8 * 64;
                split_pair(acc[mt][j][2], acc[mt][j][3], hp, lp);
                *(u32*)&outh[base8] = hp;
                *(u32*)&outl[base8] = lp;
            }
        }
    }
}

// ================================================================================
// Fused flash attention, ldmatrix fragments, Q frags hoisted to registers.
// smem byte offsets: Qh 0, Ql 18432, Kh 36864+st*18432, Kl 73728+st*18432,
//                    Vh 110592+st*17408, Vl 145408+st*17408, mask @180224.
// ================================================================================
#define QK_STRIDE 72
#define V_STRIDE  136
#define F_QH 0
#define F_QL 9216
#define F_KH 18432
#define F_KL 36864
#define F_VH 55296
#define F_VL 72704
#define FLASH_SMEM 181248

__global__ __launch_bounds__(256, 1) void flash_kernel(const float* __restrict__ mask,
                                                       const float* __restrict__ gate) {
    extern __shared__ char smraw[];
    __nv_bfloat16* S = (__nv_bfloat16*)smraw;
    float* maskS = (float*)(smraw + 180224);

    const int bm = blockIdx.x * 128;
    const int bh = blockIdx.y;
    const int b = bh >> 4, h = bh & 15;

    const int tid = threadIdx.x;
    const int lane = tid & 31, warp = tid >> 5;
    const int g = lane >> 2, c = lane & 3;
    const int mr = warp * 16;

    const u32 sb = smem_u32(smraw);
    const int lrA = lane & 15, lcA = (lane >> 4) << 3;
    const int lrB = (lane & 7) | ((lane >> 4) << 3);
    const int lcB = ((lane >> 3) & 1) << 3;
    const u32 qAddrH = sb + (u32)((mr + lrA) * 144 + lcA * 2);
    const u32 qAddrL = qAddrH + 18432u;
    const u32 kAddrH = sb + 36864u + (u32)(lrB * 144 + lcB * 2);
    const u32 kAddrL = kAddrH + 36864u;
    const u32 vAddrH = sb + 110592u + (u32)(lrB * 272 + lcB * 2);
    const u32 vAddrL = vAddrH + 34816u;

    // prologue: Q + stage 0 K/V/mask in one group
    {
        const size_t qbase = ((size_t)bh * SEQ + bm) * 64;
#pragma unroll
        for (int i = 0; i < 4; i++) {
            int idx = tid + i * 256;
            int row = idx >> 3, seg = idx & 7;
            cp16(S + F_QH + row * QK_STRIDE + seg * 8, g_Qh + qbase + (size_t)row * 64 + seg * 8);
            cp16(S + F_QL + row * QK_STRIDE + seg * 8, g_Ql + qbase + (size_t)row * 64 + seg * 8);
        }
        const size_t kbase = (size_t)bh * SEQ * 64;
#pragma unroll
        for (int i = 0; i < 4; i++) {
            int idx = tid + i * 256;
            int row = idx >> 3, seg = idx & 7;
            cp16(S + F_KH + row * QK_STRIDE + seg * 8, g_Kh + kbase + (size_t)row * 64 + seg * 8);
            cp16(S + F_KL + row * QK_STRIDE + seg * 8, g_Kl + kbase + (size_t)row * 64 + seg * 8);
        }
        const size_t vbase = (size_t)bh * 64 * 2048;
#pragma unroll
        for (int i = 0; i < 4; i++) {
            int idx = tid + i * 256;
            int d = idx >> 4, seg = idx & 15;
            cp16(S + F_VH + d * V_STRIDE + seg * 8, g_Vh + vbase + (size_t)d * 2048 + seg * 8);
            cp16(S + F_VL + d * V_STRIDE + seg * 8, g_Vl + vbase + (size_t)d * 2048 + seg * 8);
        }
        if (tid < 32) cp16(maskS + tid * 4, mask + b * SEQ + tid * 4);
        cp_commit();
    }
    cp_wait0();
    __syncthreads();

    // hoist Q fragments
    u32 qH[4][4], qL[4][4];
#pragma unroll
    for (int kk = 0; kk < 4; kk++) {
        ldsm4(qH[kk], qAddrH + kk * 32);
        ldsm4(qL[kk], qAddrL + kk * 32);
    }

    float o[8][4];
#pragma unroll
    for (int j = 0; j < 8; j++)
#pragma unroll
        for (int q = 0; q < 4; q++) o[j][q] = 0.0f;
    float m0 = -1e30f, m1 = -1e30f, l0 = 0.0f, l1 = 0.0f;

    for (int it = 0; it < 16; it++) {
        const int cur = it & 1;
        if (it + 1 < 16) {
            const int st = cur ^ 1;
            const int t0 = (it + 1) * 128;
            const size_t kbase = ((size_t)bh * SEQ + t0) * 64;
#pragma unroll
            for (int i = 0; i < 4; i++) {
                int idx = tid + i * 256;
                int row = idx >> 3, seg = idx & 7;
                cp16(S + F_KH + st * 9216 + row * QK_STRIDE + seg * 8,
                     g_Kh + kbase + (size_t)row * 64 + seg * 8);
                cp16(S + F_KL + st * 9216 + row * QK_STRIDE + seg * 8,
                     g_Kl + kbase + (size_t)row * 64 + seg * 8);
            }
            const size_t vbase = (size_t)bh * 64 * 2048 + t0;
#pragma unroll
            for (int i = 0; i < 4; i++) {
                int idx = tid + i * 256;
                int d = idx >> 4, seg = idx & 15;
                cp16(S + F_VH + st * 8704 + d * V_STRIDE + seg * 8,
                     g_Vh + vbase + (size_t)d * 2048 + seg * 8);
                cp16(S + F_VL + st * 8704 + d * V_STRIDE + seg * 8,
                     g_Vl + vbase + (size_t)d * 2048 + seg * 8);
            }
            if (tid < 32) cp16(maskS + st * 128 + tid * 4, mask + b * SEQ + t0 + tid * 4);
            cp_commit();
            cp_wait1();
        } else {
            cp_wait0();
        }
        __syncthreads();

        const u32 kStH = kAddrH + (u32)(cur * 18432);
        const u32 kStL = kAddrL + (u32)(cur * 18432);
        const u32 vStH = vAddrH + (u32)(cur * 17408);
        const u32 vStL = vAddrL + (u32)(cur * 17408);
        const float* mk = maskS + cur * 128;

        // ---- S = Q K^T (split) ----
        float s[16][4];
#pragma unroll
        for (int j = 0; j < 16; j++)
#pragma unroll
            for (int q = 0; q < 4; q++) s[j][q] = 0.0f;

#pragma unroll
        for (int kk = 0; kk < 4; kk++) {
#pragma unroll
            for (int jj = 0; jj < 8; jj++) {
                u32 kh[4], kl[4];
                ldsm4(kh, kStH + jj * 2304 + kk * 32);
                ldsm4(kl, kStL + jj * 2304 + kk * 32);
                float* s0 = s[2 * jj];
                float* s1 = s[2 * jj + 1];
                mma16816(s0, qH[kk][0], qH[kk][1], qH[kk][2], qH[kk][3], kh[0], kh[1]);
                mma16816(s0, qH[kk][0], qH[kk][1], qH[kk][2], qH[kk][3], kl[0], kl[1]);
                mma16816(s0, qL[kk][0], qL[kk][1], qL[kk][2], qL[kk][3], kh[0], kh[1]);
                mma16816(s1, qH[kk][0], qH[kk][1], qH[kk][2], qH[kk][3], kh[2], kh[3]);
                mma16816(s1, qH[kk][0], qH[kk][1], qH[kk][2], qH[kk][3], kl[2], kl[3]);
                mma16816(s1, qL[kk][0], qL[kk][1], qL[kk][2], qL[kk][3], kh[2], kh[3]);
            }
        }

        // ---- scale + mask ----
#pragma unroll
        for (int j = 0; j < 16; j++) {
            float mk0 = mk[j * 8 + 2 * c];
            float mk1 = mk[j * 8 + 2 * c + 1];
            s[j][0] = s[j][0] * 0.125f + mk0;
            s[j][1] = s[j][1] * 0.125f + mk1;
            s[j][2] = s[j][2] * 0.125f + mk0;
            s[j][3] = s[j][3] * 0.125f + mk1;
        }

        // ---- online softmax ----
        float mt0 = -1e30f, mt1 = -1e30f;
#pragma unroll
        for (int j = 0; j < 16; j++) {
            mt0 = fmaxf(mt0, fmaxf(s[j][0], s[j][1]));
            mt1 = fmaxf(mt1, fmaxf(s[j][2], s[j][3]));
        }
        mt0 = fmaxf(mt0, __shfl_xor_sync(0xffffffffu, mt0, 1));
        mt0 = fmaxf(mt0, __shfl_xor_sync(0xffffffffu, mt0, 2));
        mt1 = fmaxf(mt1, __shfl_xor_sync(0xffffffffu, mt1, 1));
        mt1 = fmaxf(mt1, __shfl_xor_sync(0xffffffffu, mt1, 2));
        float mn0 = fmaxf(m0, mt0), mn1 = fmaxf(m1, mt1);
        float al0 = __expf(m0 - mn0), al1 = __expf(m1 - mn1);
        m0 = mn0; m1 = mn1;

        float rs0 = 0.0f, rs1 = 0.0f;
#pragma unroll
        for (int j = 0; j < 16; j++) {
            s[j][0] = __expf(s[j][0] - mn0); rs0 += s[j][0];
            s[j][1] = __expf(s[j][1] - mn0); rs0 += s[j][1];
            s[j][2] = __expf(s[j][2] - mn1); rs1 += s[j][2];
            s[j][3] = __expf(s[j][3] - mn1); rs1 += s[j][3];
        }
        rs0 += __shfl_xor_sync(0xffffffffu, rs0, 1);
        rs0 += __shfl_xor_sync(0xffffffffu, rs0, 2);
        rs1 += __shfl_xor_sync(0xffffffffu, rs1, 1);
        rs1 += __shfl_xor_sync(0xffffffffu, rs1, 2);
        l0 = l0 * al0 + rs0;
        l1 = l1 * al1 + rs1;
#pragma unroll
        for (int j = 0; j < 8; j++) {
            o[j][0] *= al0; o[j][1] *= al0;
            o[j][2] *= al1; o[j][3] *= al1;
        }

        // ---- O += P V (split) ----
#pragma unroll
        for (int kk = 0; kk < 8; kk++) {
            u32 pa0, pa1, pa2, pa3, pb0, pb1, pb2, pb3;
            split_pair(s[2 * kk][0], s[2 * kk][1], pa0, pb0);
            split_pair(s[2 * kk][2], s[2 * kk][3], pa1, pb1);
            split_pair(s[2 * kk + 1][0], s[2 * kk + 1][1], pa2, pb2);
            split_pair(s[2 * kk + 1][2], s[2 * kk + 1][3], pa3, pb3);
#pragma unroll
            for (int jj = 0; jj < 4; jj++) {
                u32 vh[4], vl[4];
                ldsm4(vh, vStH + jj * 4352 + kk * 32);
                ldsm4(vl, vStL + jj * 4352 + kk * 32);
                float* o0 = o[2 * jj];
                float* o1 = o[2 * jj + 1];
                mma16816(o0, pa0, pa1, pa2, pa3, vh[0], vh[1]);
                mma16816(o0, pa0, pa1, pa2, pa3, vl[0], vl[1]);
                mma16816(o0, pb0, pb1, pb2, pb3, vh[0], vh[1]);
                mma16816(o1, pa0, pa1, pa2, pa3, vh[2], vh[3]);
                mma16816(o1, pa0, pa1, pa2, pa3, vl[2], vl[3]);
                mma16816(o1, pb0, pb1, pb2, pb3, vh[2], vh[3]);
            }
        }
        __syncthreads();
    }

    // ---- epilogue ----
    float gv = gate[h];
    float eff = (gv >= GATE_EPS) ? gv : 0.0f;
    float inv0 = eff / l0, inv1 = eff / l1;
    int row0 = bm + mr + g;
#pragma unroll
    for (int j = 0; j < 8; j++) {
        int e0 = h * 64 + j * 8 + 2 * c;
        size_t base0 = ((size_t)b * SEQ + row0) * 1024 + e0;
        size_t base1 = ((size_t)b * SEQ + row0 + 8) * 1024 + e0;
        u32 hp, lp;
        split_pair(o[j][0] * inv0, o[j][1] * inv0, hp, lp);
        *(u32*)&g_Ch[base0] = hp;
        *(u32*)&g_Cl[base0] = lp;
        split_pair(o[j][2] * inv1, o[j][3] * inv1, hp, lp);
        *(u32*)&g_Ch[base1] = hp;
        *(u32*)&g_Cl[base1] = lp;
    }
}

// ================================================================================
extern "C" void kernel_launch(void* const* d_in, const int* in_sizes, int n_in,
                              void* d_out, int out_size) {
    const float* X    = (const float*)d_in[0];
    const float* mask = (const float*)d_in[1];
    const float* Wq   = (const float*)d_in[2];
    const float* Wk   = (const float*)d_in[3];
    const float* Wv   = (const float*)d_in[4];
    const float* Wo   = (const float*)d_in[5];
    const float* gate = (const float*)d_in[6];
    float* out = (float*)d_out;

    cudaFuncSetAttribute(gemm_kernel, cudaFuncAttributeMaxDynamicSharedMemorySize, GEMM_SMEM);
    cudaFuncSetAttribute(flash_kernel, cudaFuncAttributeMaxDynamicSharedMemorySize, FLASH_SMEM);

    prep_x_kernel<<<16384, 256>>>(X);
    transpose_wqkv_kernel<<<dim3(2, 32, 48), dim3(32, 8)>>>(Wq, Wk, Wv);
    transpose_wo_kernel<<<dim3(32, 32), dim3(32, 8)>>>(Wo);
    gemm_kernel<<<dim3(32, 8, 3), 256, GEMM_SMEM>>>(-1, gate, out);   // QKV
    flash_kernel<<<dim3(16, 32), 256, FLASH_SMEM>>>(mask, gate);
    gemm_kernel<<<dim3(32, 8, 1), 256, GEMM_SMEM>>>(3, gate, out);    // O proj
}

// round 6
// speedup vs baseline: 3.4874x; 1.0056x over previous
#include <cuda_runtime.h>
#include <cuda_bf16.h>
#include <math.h>

#define BATCH 2
#define NHEAD 16
#define SEQ   2048
#define EMB   1024
#define HDIM  64
#define GATE_EPS 1e-4f

typedef unsigned int u32;

// ------------------ scratch (bf16 hi/lo splits) ------------------
__device__ __nv_bfloat16 g_Xh[4096 * 1024];
__device__ __nv_bfloat16 g_Xl[4096 * 1024];
__device__ __nv_bfloat16 g_Wh[4 * 1024 * 1024];
__device__ __nv_bfloat16 g_Wl[4 * 1024 * 1024];
__device__ __nv_bfloat16 g_Qh[32 * 2048 * 64];
__device__ __nv_bfloat16 g_Ql[32 * 2048 * 64];
__device__ __nv_bfloat16 g_Kh[32 * 2048 * 64];
__device__ __nv_bfloat16 g_Kl[32 * 2048 * 64];
__device__ __nv_bfloat16 g_Vh[32 * 64 * 2048];
__device__ __nv_bfloat16 g_Vl[32 * 64 * 2048];
__device__ __nv_bfloat16 g_Ch[4096 * 1024];
__device__ __nv_bfloat16 g_Cl[4096 * 1024];

// ------------------------------- helpers ---------------------------------------
__device__ __forceinline__ void split_pair(float x, float y, u32 &hi, u32 &lo) {
    __nv_bfloat16 hx = __float2bfloat16(x);
    __nv_bfloat16 hy = __float2bfloat16(y);
    __nv_bfloat16 lx = __float2bfloat16(x - __bfloat162float(hx));
    __nv_bfloat16 ly = __float2bfloat16(y - __bfloat162float(hy));
    __nv_bfloat162 hp = __halves2bfloat162(hx, hy);
    __nv_bfloat162 lp = __halves2bfloat162(lx, ly);
    hi = *reinterpret_cast<u32*>(&hp);
    lo = *reinterpret_cast<u32*>(&lp);
}

__device__ __forceinline__ void split1(float x, __nv_bfloat16 &h, __nv_bfloat16 &l) {
    h = __float2bfloat16(x);
    l = __float2bfloat16(x - __bfloat162float(h));
}

// NOTE: non-volatile — pure register computation; lets ptxas schedule HMMAs.
__device__ __forceinline__ void mma16816(float* d, u32 a0, u32 a1, u32 a2, u32 a3,
                                         u32 b0, u32 b1) {
    asm("mma.sync.aligned.m16n8k16.row.col.f32.bf16.bf16.f32 "
        "{%0,%1,%2,%3}, {%4,%5,%6,%7}, {%8,%9}, {%0,%1,%2,%3};\n"
        : "+f"(d[0]), "+f"(d[1]), "+f"(d[2]), "+f"(d[3])
        : "r"(a0), "r"(a1), "r"(a2), "r"(a3), "r"(b0), "r"(b1));
}

__device__ __forceinline__ void ldsm4(u32* r, u32 saddr) {
    asm volatile(
        "ldmatrix.sync.aligned.m8n8.x4.shared.b16 {%0,%1,%2,%3}, [%4];"
        : "=r"(r[0]), "=r"(r[1]), "=r"(r[2]), "=r"(r[3]) : "r"(saddr));
}

__device__ __forceinline__ u32 smem_u32(const void* p) {
    return (u32)__cvta_generic_to_shared(p);
}

__device__ __forceinline__ void cp16(void* dst, const void* src) {
    u32 d = (u32)__cvta_generic_to_shared(dst);
    asm volatile("cp.async.cg.shared.global [%0], [%1], 16;\n" :: "r"(d), "l"(src));
}
__device__ __forceinline__ void cp_commit() { asm volatile("cp.async.commit_group;\n"); }
__device__ __forceinline__ void cp_wait1()  { asm volatile("cp.async.wait_group 1;\n"); }
__device__ __forceinline__ void cp_wait0()  { asm volatile("cp.async.wait_group 0;\n"); }

// ================================================================================
__global__ __launch_bounds__(256) void prep_x_kernel(const float* __restrict__ X) {
    int idx = blockIdx.x * 256 + threadIdx.x;
    float x = X[idx];
    __nv_bfloat16 h = __float2bfloat16(x);
    g_Xh[idx] = h;
    g_Xl[idx] = __float2bfloat16(x - __bfloat162float(h));
}

__global__ void transpose_wqkv_kernel(const float* __restrict__ Wq,
                                      const float* __restrict__ Wk,
                                      const float* __restrict__ Wv) {
    __shared__ float tile[32][33];
    int z = blockIdx.z;
    int w = z >> 4, h = z & 15;
    const float* in = ((w == 0) ? Wq : (w == 1) ? Wk : Wv) + (size_t)h * EMB * HDIM;
    __nv_bfloat16* oh = g_Wh + (size_t)w * 1048576 + (size_t)h * 64 * 1024;
    __nv_bfloat16* ol = g_Wl + (size_t)w * 1048576 + (size_t)h * 64 * 1024;
    int e0 = blockIdx.y * 32, d0 = blockIdx.x * 32;
    for (int i = threadIdx.y; i < 32; i += 8)
        tile[i][threadIdx.x] = in[(size_t)(e0 + i) * HDIM + d0 + threadIdx.x];
    __syncthreads();
    for (int i = threadIdx.y; i < 32; i += 8) {
        float v = tile[threadIdx.x][i];
        __nv_bfloat16 hh = __float2bfloat16(v);
        oh[(size_t)(d0 + i) * 1024 + e0 + threadIdx.x] = hh;
        ol[(size_t)(d0 + i) * 1024 + e0 + threadIdx.x] =
            __float2bfloat16(v - __bfloat162float(hh));
    }
}

__global__ void transpose_wo_kernel(const float* __restrict__ Wo) {
    __shared__ float tile[32][33];
    __nv_bfloat16* oh = g_Wh + 3u * 1048576;
    __nv_bfloat16* ol = g_Wl + 3u * 1048576;
    int k0 = blockIdx.y * 32, n0 = blockIdx.x * 32;
    for (int i = threadIdx.y; i < 32; i += 8)
        tile[i][threadIdx.x] = Wo[(size_t)(k0 + i) * 1024 + n0 + threadIdx.x];
    __syncthreads();
    for (int i = threadIdx.y; i < 32; i += 8) {
        float v = tile[threadIdx.x][i];
        __nv_bfloat16 hh = __float2bfloat16(v);
        oh[(size_t)(n0 + i) * 1024 + k0 + threadIdx.x] = hh;
        ol[(size_t)(n0 + i) * 1024 + k0 + threadIdx.x] =
            __float2bfloat16(v - __bfloat162float(hh));
    }
}

// ================================================================================
// Split-bf16 GEMM.  Inner loop issues independent-accumulator MMA waves:
// all hi*hi first, then hi*lo, then lo*hi -> dependent-chain distance >= 4.
// ================================================================================
#define GEMM_SMEM 81920
#define ST_STRIDE 20480
#define ST_BYTES  40960

__global__ __launch_bounds__(256, 2) void gemm_kernel(int mode,
                                                      const float* __restrict__ gate,
                                                      float* __restrict__ out) {
    extern __shared__ __nv_bfloat16 sm[];
    if (mode < 0) mode = blockIdx.z;

    const int bm = blockIdx.x * 128;
    const int bn = blockIdx.y * 128;

    const __nv_bfloat16 *pAh, *pAl, *pBh, *pBl;
    if (mode < 3) {
        pAh = g_Xh; pAl = g_Xl;
        pBh = g_Wh + (size_t)mode * 1048576;
        pBl = g_Wl + (size_t)mode * 1048576;
    } else {
        pAh = g_Ch; pAl = g_Cl;
        pBh = g_Wh + 3u * 1048576;
        pBl = g_Wl + 3u * 1048576;
    }

    const int tid = threadIdx.x;
    const int lane = tid & 31, warp = tid >> 5;
    const int wr = warp & 3, wc = warp >> 2;
    const int g = lane >> 2, c = lane & 3;

    const int lrow = tid >> 1;
    const int lseg0 = (tid & 1) * 2;

    const u32 smb = smem_u32(sm);
    const int lrA = lane & 15, lcA = (lane >> 4) << 3;
    const int lrB = (lane & 7) | ((lane >> 4) << 3);
    const int lcB = ((lane >> 3) & 1) << 3;
    const u32 offA = smb + (u32)(((wr * 32 + lrA) * 40 + lcA) * 2);
    const u32 offB = smb + 20480u + (u32)(((wc * 64 + lrB) * 40 + lcB) * 2);

    float acc[2][8][4];
#pragma unroll
    for (int mt = 0; mt < 2; mt++)
#pragma unroll
        for (int j = 0; j < 8; j++)
#pragma unroll
            for (int q = 0; q < 4; q++) acc[mt][j][q] = 0.0f;

    {
#pragma unroll
        for (int i = 0; i < 2; i++) {
            int seg = lseg0 + i;
            int off = lrow * 40 + seg * 8;
            size_t asrc = (size_t)(bm + lrow) * 1024 + seg * 8;
            size_t bsrc = (size_t)(bn + lrow) * 1024 + seg * 8;
            cp16(sm + off, pAh + asrc);
            cp16(sm + 5120 + off, pAl + asrc);
            cp16(sm + 10240 + off, pBh + bsrc);
            cp16(sm + 15360 + off, pBl + bsrc);
        }
        cp_commit();
    }

    for (int it = 0; it < 32; it++) {
        const int cur = it & 1;
        if (it + 1 < 32) {
            const int k0 = (it + 1) * 32;
            __nv_bfloat16* base = sm + (cur ^ 1) * ST_STRIDE;
#pragma unroll
            for (int i = 0; i < 2; i++) {
                int seg = lseg0 + i;
                int off = lrow * 40 + seg * 8;
                size_t asrc = (size_t)(bm + lrow) * 1024 + k0 + seg * 8;
                size_t bsrc = (size_t)(bn + lrow) * 1024 + k0 + seg * 8;
                cp16(base + off, pAh + asrc);
                cp16(base + 5120 + off, pAl + asrc);
                cp16(base + 10240 + off, pBh + bsrc);
                cp16(base + 15360 + off, pBl + bsrc);
            }
            cp_commit();
            cp_wait1();
        } else {
            cp_wait0();
        }
        __syncthreads();

        const u32 stb = (u32)(cur * ST_BYTES);
#pragma unroll
        for (int kk = 0; kk < 2; kk++) {
            u32 aH[2][4], aL[2][4];
#pragma unroll
            for (int mt = 0; mt < 2; mt++) {
                ldsm4(aH[mt], offA + stb + mt * 1280 + kk * 32);
                ldsm4(aL[mt], offA + stb + 10240 + mt * 1280 + kk * 32);
            }
#pragma unroll
            for (int jj = 0; jj < 4; jj++) {
                u32 bH[4], bL[4];
                ldsm4(bH, offB + stb + jj * 1280 + kk * 32);
                ldsm4(bL, offB + stb + 10240 + jj * 1280 + kk * 32);
                // wave 1: hi*hi for 4 independent accumulators
#pragma unroll
                for (int mt = 0; mt < 2; mt++) {
                    mma16816(acc[mt][2 * jj],     aH[mt][0], aH[mt][1], aH[mt][2], aH[mt][3], bH[0], bH[1]);
                    mma16816(acc[mt][2 * jj + 1], aH[mt][0], aH[mt][1], aH[mt][2], aH[mt][3], bH[2], bH[3]);
                }
                // wave 2: hi*lo
#pragma unroll
                for (int mt = 0; mt < 2; mt++) {
                    mma16816(acc[mt][2 * jj],     aH[mt][0], aH[mt][1], aH[mt][2], aH[mt][3], bL[0], bL[1]);
                    mma16816(acc[mt][2 * jj + 1], aH[mt][0], aH[mt][1], aH[mt][2], aH[mt][3], bL[2], bL[3]);
                }
                // wave 3: lo*hi
#pragma unroll
                for (int mt = 0; mt < 2; mt++) {
                    mma16816(acc[mt][2 * jj],     aL[mt][0], aL[mt][1], aL[mt][2], aL[mt][3], bH[0], bH[1]);
                    mma16816(acc[mt][2 * jj + 1], aL[mt][0], aL[mt][1], aL[mt][2], aL[mt][3], bH[2], bH[3]);
                }
            }
        }
        __syncthreads();
    }

    // ---------------- epilogues ----------------
    if (mode == 3) {
        int cnt = 0;
#pragma unroll
        for (int i = 0; i < NHEAD; i++) cnt += (gate[i] > GATE_EPS) ? 1 : 0;
        float scale = (cnt > 0) ? 1.0f / fmaxf(1.0f, (float)cnt / (float)NHEAD) : 1.0f;
#pragma unroll
        for (int mt = 0; mt < 2; mt++) {
            int row = bm + wr * 32 + mt * 16 + g;
#pragma unroll
            for (int j = 0; j < 8; j++) {
                int n0 = bn + wc * 64 + j * 8 + 2 * c;
                float2 v0 = make_float2(acc[mt][j][0] * scale, acc[mt][j][1] * scale);
                float2 v1 = make_float2(acc[mt][j][2] * scale, acc[mt][j][3] * scale);
                *(float2*)&out[(size_t)row * 1024 + n0] = v0;
                *(float2*)&out[(size_t)(row + 8) * 1024 + n0] = v1;
            }
        }
    } else if (mode == 2) {
#pragma unroll
        for (int mt = 0; mt < 2; mt++) {
            int row = bm + wr * 32 + mt * 16 + g;
            int b = row >> 11, s = row & (SEQ - 1);
#pragma unroll
            for (int j = 0; j < 8; j++) {
                int n0 = bn + wc * 64 + j * 8 + 2 * c;
                int h = n0 >> 6, d = n0 & 63;
                size_t vb = (size_t)(b * 16 + h) * 64;
                __nv_bfloat16 vh, vl;
                split1(acc[mt][j][0], vh, vl);
                g_Vh[(vb + d) * 2048 + s] = vh;  g_Vl[(vb + d) * 2048 + s] = vl;
                split1(acc[mt][j][1], vh, vl);
                g_Vh[(vb + d + 1) * 2048 + s] = vh;  g_Vl[(vb + d + 1) * 2048 + s] = vl;
                split1(acc[mt][j][2], vh, vl);
                g_Vh[(vb + d) * 2048 + s + 8] = vh;  g_Vl[(vb + d) * 2048 + s + 8] = vl;
                split1(acc[mt][j][3], vh, vl);
                g_Vh[(vb + d + 1) * 2048 + s + 8] = vh;  g_Vl[(vb + d + 1) * 2048 + s + 8] = vl;
            }
        }
    } else {
        __nv_bfloat16* outh = (mode == 0) ? g_Qh : g_Kh;
        __nv_bfloat16* outl = (mode == 0) ? g_Ql : g_Kl;
#pragma unroll
        for (int mt = 0; mt < 2; mt++) {
            int row = bm + wr * 32 + mt * 16 + g;
            int b = row >> 11, s = row & (SEQ - 1);
#pragma unroll
            for (int j = 0; j < 8; j++) {
                int n0 = bn + wc * 64 + j * 8 + 2 * c;
                int h = n0 >> 6, d = n0 & 63;
                size_t base = (((size_t)(b * 16 + h)) * SEQ + s) * 64 + d;
                u32 hp, lp;
                split_pair(acc[mt][j][0], acc[mt][j][1], hp, lp);
                *(u32*)&outh[base] = hp;
                *(u32*)&outl[base] = lp;
                size_t base8 = base + 8 * 64;
                split_pair(acc[mt][j][2], acc[mt][j][3], hp, lp);
                *(u32*)&outh[base8] = hp;
                *(u32*)&outl[base8] = lp;
            }
        }
    }
}

// ================================================================================
// Fused flash attention — same ILP restructuring in QK and PV loops.
// ================================================================================
#define QK_STRIDE 72
#define V_STRIDE  136
#define F_QH 0
#define F_QL 9216
#define F_KH 18432
#define F_KL 36864
#define F_VH 55296
#define F_VL 72704
#define FLASH_SMEM 181248

__global__ __launch_bounds__(256, 1) void flash_kernel(const float* __restrict__ mask,
                                                       const float* __restrict__ gate) {
    extern __shared__ char smraw[];
    __nv_bfloat16* S = (__nv_bfloat16*)smraw;
    float* maskS = (float*)(smraw + 180224);

    const int bm = blockIdx.x * 128;
    const int bh = blockIdx.y;
    const int b = bh >> 4, h = bh & 15;

    const int tid = threadIdx.x;
    const int lane = tid & 31, warp = tid >> 5;
    const int g = lane >> 2, c = lane & 3;
    const int mr = warp * 16;

    const u32 sb = smem_u32(smraw);
    const int lrA = lane & 15, lcA = (lane >> 4) << 3;
    const int lrB = (lane & 7) | ((lane >> 4) << 3);
    const int lcB = ((lane >> 3) & 1) << 3;
    const u32 qAddrH = sb + (u32)((mr + lrA) * 144 + lcA * 2);
    const u32 qAddrL = qAddrH + 18432u;
    const u32 kAddrH = sb + 36864u + (u32)(lrB * 144 + lcB * 2);
    const u32 kAddrL = kAddrH + 36864u;
    const u32 vAddrH = sb + 110592u + (u32)(lrB * 272 + lcB * 2);
    const u32 vAddrL = vAddrH + 34816u;

    {
        const size_t qbase = ((size_t)bh * SEQ + bm) * 64;
#pragma unroll
        for (int i = 0; i < 4; i++) {
            int idx = tid + i * 256;
            int row = idx >> 3, seg = idx & 7;
            cp16(S + F_QH + row * QK_STRIDE + seg * 8, g_Qh + qbase + (size_t)row * 64 + seg * 8);
            cp16(S + F_QL + row * QK_STRIDE + seg * 8, g_Ql + qbase + (size_t)row * 64 + seg * 8);
        }
        const size_t kbase = (size_t)bh * SEQ * 64;
#pragma unroll
        for (int i = 0; i < 4; i++) {
            int idx = tid + i * 256;
            int row = idx >> 3, seg = idx & 7;
            cp16(S + F_KH + row * QK_STRIDE + seg * 8, g_Kh + kbase + (size_t)row * 64 + seg * 8);
            cp16(S + F_KL + row * QK_STRIDE + seg * 8, g_Kl + kbase + (size_t)row * 64 + seg * 8);
        }
        const size_t vbase = (size_t)bh * 64 * 2048;
#pragma unroll
        for (int i = 0; i < 4; i++) {
            int idx = tid + i * 256;
            int d = idx >> 4, seg = idx & 15;
            cp16(S + F_VH + d * V_STRIDE + seg * 8, g_Vh + vbase + (size_t)d * 2048 + seg * 8);
            cp16(S + F_VL + d * V_STRIDE + seg * 8, g_Vl + vbase + (size_t)d * 2048 + seg * 8);
        }
        if (tid < 32) cp16(maskS + tid * 4, mask + b * SEQ + tid * 4);
        cp_commit();
    }
    cp_wait0();
    __syncthreads();

    u32 qH[4][4], qL[4][4];
#pragma unroll
    for (int kk = 0; kk < 4; kk++) {
        ldsm4(qH[kk], qAddrH + kk * 32);
        ldsm4(qL[kk], qAddrL + kk * 32);
    }

    float o[8][4];
#pragma unroll
    for (int j = 0; j < 8; j++)
#pragma unroll
        for (int q = 0; q < 4; q++) o[j][q] = 0.0f;
    float m0 = -1e30f, m1 = -1e30f, l0 = 0.0f, l1 = 0.0f;

    for (int it = 0; it < 16; it++) {
        const int cur = it & 1;
        if (it + 1 < 16) {
            const int st = cur ^ 1;
            const int t0 = (it + 1) * 128;
            const size_t kbase = ((size_t)bh * SEQ + t0) * 64;
#pragma unroll
            for (int i = 0; i < 4; i++) {
                int idx = tid + i * 256;
                int row = idx >> 3, seg = idx & 7;
                cp16(S + F_KH + st * 9216 + row * QK_STRIDE + seg * 8,
                     g_Kh + kbase + (size_t)row * 64 + seg * 8);
                cp16(S + F_KL + st * 9216 + row * QK_STRIDE + seg * 8,
                     g_Kl + kbase + (size_t)row * 64 + seg * 8);
            }
            const size_t vbase = (size_t)bh * 64 * 2048 + t0;
#pragma unroll
            for (int i = 0; i < 4; i++) {
                int idx = tid + i * 256;
                int d = idx >> 4, seg = idx & 15;
                cp16(S + F_VH + st * 8704 + d * V_STRIDE + seg * 8,
                     g_Vh + vbase + (size_t)d * 2048 + seg * 8);
                cp16(S + F_VL + st * 8704 + d * V_STRIDE + seg * 8,
                     g_Vl + vbase + (size_t)d * 2048 + seg * 8);
            }
            if (tid < 32) cp16(maskS + st * 128 + tid * 4, mask + b * SEQ + t0 + tid * 4);
            cp_commit();
            cp_wait1();
        } else {
            cp_wait0();
        }
        __syncthreads();

        const u32 kStH = kAddrH + (u32)(cur * 18432);
        const u32 kStL = kAddrL + (u32)(cur * 18432);
        const u32 vStH = vAddrH + (u32)(cur * 17408);
        const u32 vStL = vAddrL + (u32)(cur * 17408);
        const float* mk = maskS + cur * 128;

        float s[16][4];
#pragma unroll
        for (int j = 0; j < 16; j++)
#pragma unroll
            for (int q = 0; q < 4; q++) s[j][q] = 0.0f;

#pragma unroll
        for (int kk = 0; kk < 4; kk++) {
#pragma unroll
            for (int jj = 0; jj < 8; jj += 2) {
                u32 kh0[4], kl0[4], kh1[4], kl1[4];
                ldsm4(kh0, kStH + jj * 2304 + kk * 32);
                ldsm4(kl0, kStL + jj * 2304 + kk * 32);
                ldsm4(kh1, kStH + (jj + 1) * 2304 + kk * 32);
                ldsm4(kl1, kStL + (jj + 1) * 2304 + kk * 32);
                float* s0 = s[2 * jj];
                float* s1 = s[2 * jj + 1];
                float* s2 = s[2 * jj + 2];
                float* s3 = s[2 * jj + 3];
                // wave 1: hi*hi into 4 independent accumulators
                mma16816(s0, qH[kk][0], qH[kk][1], qH[kk][2], qH[kk][3], kh0[0], kh0[1]);
                mma16816(s1, qH[kk][0], qH[kk][1], qH[kk][2], qH[kk][3], kh0[2], kh0[3]);
                mma16816(s2, qH[kk][0], qH[kk][1], qH[kk][2], qH[kk][3], kh1[0], kh1[1]);
                mma16816(s3, qH[kk][0], qH[kk][1], qH[kk][2], qH[kk][3], kh1[2], kh1[3]);
                // wave 2: hi*lo
                mma16816(s0, qH[kk][0], qH[kk][1], qH[kk][2], qH[kk][3], kl0[0], kl0[1]);
                mma16816(s1, qH[kk][0], qH[kk][1], qH[kk][2], qH[kk][3], kl0[2], kl0[3]);
                mma16816(s2, qH[kk][0], qH[kk][1], qH[kk][2], qH[kk][3], kl1[0], kl1[1]);
                mma16816(s3, qH[kk][0], qH[kk][1], qH[kk][2], qH[kk][3], kl1[2], kl1[3]);
                // wave 3: lo*hi
                mma16816(s0, qL[kk][0], qL[kk][1], qL[kk][2], qL[kk][3], kh0[0], kh0[1]);
                mma16816(s1, qL[kk][0], qL[kk][1], qL[kk][2], qL[kk][3], kh0[2], kh0[3]);
                mma16816(s2, qL[kk][0], qL[kk][1], qL[kk][2], qL[kk][3], kh1[0], kh1[1]);
                mma16816(s3, qL[kk][0], qL[kk][1], qL[kk][2], qL[kk][3], kh1[2], kh1[3]);
            }
        }

#pragma unroll
        for (int j = 0; j < 16; j++) {
            float mk0 = mk[j * 8 + 2 * c];
            float mk1 = mk[j * 8 + 2 * c + 1];
            s[j][0] = s[j][0] * 0.125f + mk0;
            s[j][1] = s[j][1] * 0.125f + mk1;
            s[j][2] = s[j][2] * 0.125f + mk0;
            s[j][3] = s[j][3] * 0.125f + mk1;
        }

        float mt0 = -1e30f, mt1 = -1e30f;
#pragma unroll
        for (int j = 0; j < 16; j++) {
            mt0 = fmaxf(mt0, fmaxf(s[j][0], s[j][1]));
            mt1 = fmaxf(mt1, fmaxf(s[j][2], s[j][3]));
        }
        mt0 = fmaxf(mt0, __shfl_xor_sync(0xffffffffu, mt0, 1));
        mt0 = fmaxf(mt0, __shfl_xor_sync(0xffffffffu, mt0, 2));
        mt1 = fmaxf(mt1, __shfl_xor_sync(0xffffffffu, mt1, 1));
        mt1 = fmaxf(mt1, __shfl_xor_sync(0xffffffffu, mt1, 2));
        float mn0 = fmaxf(m0, mt0), mn1 = fmaxf(m1, mt1);
        float al0 = __expf(m0 - mn0), al1 = __expf(m1 - mn1);
        m0 = mn0; m1 = mn1;

        float rs0 = 0.0f, rs1 = 0.0f;
#pragma unroll
        for (int j = 0; j < 16; j++) {
            s[j][0] = __expf(s[j][0] - mn0); rs0 += s[j][0];
            s[j][1] = __expf(s[j][1] - mn0); rs0 += s[j][1];
            s[j][2] = __expf(s[j][2] - mn1); rs1 += s[j][2];
            s[j][3] = __expf(s[j][3] - mn1); rs1 += s[j][3];
        }
        rs0 += __shfl_xor_sync(0xffffffffu, rs0, 1);
        rs0 += __shfl_xor_sync(0xffffffffu, rs0, 2);
        rs1 += __shfl_xor_sync(0xffffffffu, rs1, 1);
        rs1 += __shfl_xor_sync(0xffffffffu, rs1, 2);
        l0 = l0 * al0 + rs0;
        l1 = l1 * al1 + rs1;
#pragma unroll
        for (int j = 0; j < 8; j++) {
            o[j][0] *= al0; o[j][1] *= al0;
            o[j][2] *= al1; o[j][3] *= al1;
        }

#pragma unroll
        for (int kk = 0; kk < 8; kk++) {
            u32 pa0, pa1, pa2, pa3, pb0, pb1, pb2, pb3;
            split_pair(s[2 * kk][0], s[2 * kk][1], pa0, pb0);
            split_pair(s[2 * kk][2], s[2 * kk][3], pa1, pb1);
            split_pair(s[2 * kk + 1][0], s[2 * kk + 1][1], pa2, pb2);
            split_pair(s[2 * kk + 1][2], s[2 * kk + 1][3], pa3, pb3);
#pragma unroll
            for (int jj = 0; jj < 4; jj += 2) {
                u32 vh0[4], vl0[4], vh1[4], vl1[4];
                ldsm4(vh0, vStH + jj * 4352 + kk * 32);
                ldsm4(vl0, vStL + jj * 4352 + kk * 32);
                ldsm4(vh1, vStH + (jj + 1) * 4352 + kk * 32);
                ldsm4(vl1, vStL + (jj + 1) * 4352 + kk * 32);
                float* o0 = o[2 * jj];
                float* o1 = o[2 * jj + 1];
                float* o2 = o[2 * jj + 2];
                float* o3 = o[2 * jj + 3];
                // wave 1
                mma16816(o0, pa0, pa1, pa2, pa3, vh0[0], vh0[1]);
                mma16816(o1, pa0, pa1, pa2, pa3, vh0[2], vh0[3]);
                mma16816(o2, pa0, pa1, pa2, pa3, vh1[0], vh1[1]);
                mma16816(o3, pa0, pa1, pa2, pa3, vh1[2], vh1[3]);
                // wave 2
                mma16816(o0, pa0, pa1, pa2, pa3, vl0[0], vl0[1]);
                mma16816(o1, pa0, pa1, pa2, pa3, vl0[2], vl0[3]);
                mma16816(o2, pa0, pa1, pa2, pa3, vl1[0], vl1[1]);
                mma16816(o3, pa0, pa1, pa2, pa3, vl1[2], vl1[3]);
                // wave 3
                mma16816(o0, pb0, pb1, pb2, pb3, vh0[0], vh0[1]);
                mma16816(o1, pb0, pb1, pb2, pb3, vh0[2], vh0[3]);
                mma16816(o2, pb0, pb1, pb2, pb3, vh1[0], vh1[1]);
                mma16816(o3, pb0, pb1, pb2, pb3, vh1[2], vh1[3]);
            }
        }
        __syncthreads();
    }

    float gv = gate[h];
    float eff = (gv >= GATE_EPS) ? gv : 0.0f;
    float inv0 = eff / l0, inv1 = eff / l1;
    int row0 = bm + mr + g;
#pragma unroll
    for (int j = 0; j < 8; j++) {
        int e0 = h * 64 + j * 8 + 2 * c;
        size_t base0 = ((size_t)b * SEQ + row0) * 1024 + e0;
        size_t base1 = ((size_t)b * SEQ + row0 + 8) * 1024 + e0;
        u32 hp, lp;
        split_pair(o[j][0] * inv0, o[j][1] * inv0, hp, lp);
        *(u32*)&g_Ch[base0] = hp;
        *(u32*)&g_Cl[base0] = lp;
        split_pair(o[j][2] * inv1, o[j][3] * inv1, hp, lp);
        *(u32*)&g_Ch[base1] = hp;
        *(u32*)&g_Cl[base1] = lp;
    }
}

// ================================================================================
extern "C" void kernel_launch(void* const* d_in, const int* in_sizes, int n_in,
                              void* d_out, int out_size) {
    const float* X    = (const float*)d_in[0];
    const float* mask = (const float*)d_in[1];
    const float* Wq   = (const float*)d_in[2];
    const float* Wk   = (const float*)d_in[3];
    const float* Wv   = (const float*)d_in[4];
    const float* Wo   = (const float*)d_in[5];
    const float* gate = (const float*)d_in[6];
    float* out = (float*)d_out;

    cudaFuncSetAttribute(gemm_kernel, cudaFuncAttributeMaxDynamicSharedMemorySize, GEMM_SMEM);
    cudaFuncSetAttribute(flash_kernel, cudaFuncAttributeMaxDynamicSharedMemorySize, FLASH_SMEM);

    prep_x_kernel<<<16384, 256>>>(X);
    transpose_wqkv_kernel<<<dim3(2, 32, 48), dim3(32, 8)>>>(Wq, Wk, Wv);
    transpose_wo_kernel<<<dim3(32, 32), dim3(32, 8)>>>(Wo);
    gemm_kernel<<<dim3(32, 8, 3), 256, GEMM_SMEM>>>(-1, gate, out);   // QKV
    flash_kernel<<<dim3(16, 32), 256, FLASH_SMEM>>>(mask, gate);
    gemm_kernel<<<dim3(32, 8, 1), 256, GEMM_SMEM>>>(3, gate, out);    // O proj
}

// round 7
// speedup vs baseline: 4.9281x; 1.4131x over previous
#include <cuda_runtime.h>
#include <cuda_fp16.h>
#include <math.h>

#define BATCH 2
#define NHEAD 16
#define SEQ   2048
#define EMB   1024
#define HDIM  64
#define GATE_EPS 1e-4f

typedef unsigned int u32;

// ------------------ scratch (fp16; A-side hi/lo, B-side hi only) ------------------
__device__ __half g_Xh[4096 * 1024];
__device__ __half g_Xl[4096 * 1024];
// W: slot 0..2 = Wq/Wk/Wv transposed [n=(h,d)][k=e]; slot 3 = Wo^T [n=e][k=(h,d)] (hi only)
__device__ __half g_Wh[4 * 1024 * 1024];
// Q: [b*16+h][s][d] hi/lo (A of QK^T)
__device__ __half g_Qh[32 * 2048 * 64];
__device__ __half g_Ql[32 * 2048 * 64];
// K: [b*16+h][s][d] hi only (B of QK^T)
__device__ __half g_Kh[32 * 2048 * 64];
// V TRANSPOSED: [b*16+h][d][s] hi only (B of PV)
__device__ __half g_Vh[32 * 64 * 2048];
// context: [b][s][h*64+d] hi/lo (A of O-proj)
__device__ __half g_Ch[4096 * 1024];
__device__ __half g_Cl[4096 * 1024];

// ------------------------------- helpers ---------------------------------------
__device__ __forceinline__ void split_pair(float x, float y, u32 &hi, u32 &lo) {
    __half hx = __float2half(x);
    __half hy = __float2half(y);
    __half lx = __float2half(x - __half2float(hx));
    __half ly = __float2half(y - __half2float(hy));
    __half2 hp = __halves2half2(hx, hy);
    __half2 lp = __halves2half2(lx, ly);
    hi = *reinterpret_cast<u32*>(&hp);
    lo = *reinterpret_cast<u32*>(&lp);
}

// non-volatile: lets ptxas schedule HMMAs
__device__ __forceinline__ void mma16816(float* d, u32 a0, u32 a1, u32 a2, u32 a3,
                                         u32 b0, u32 b1) {
    asm("mma.sync.aligned.m16n8k16.row.col.f32.f16.f16.f32 "
        "{%0,%1,%2,%3}, {%4,%5,%6,%7}, {%8,%9}, {%0,%1,%2,%3};\n"
        : "+f"(d[0]), "+f"(d[1]), "+f"(d[2]), "+f"(d[3])
        : "r"(a0), "r"(a1), "r"(a2), "r"(a3), "r"(b0), "r"(b1));
}

__device__ __forceinline__ void ldsm4(u32* r, u32 saddr) {
    asm volatile(
        "ldmatrix.sync.aligned.m8n8.x4.shared.b16 {%0,%1,%2,%3}, [%4];"
        : "=r"(r[0]), "=r"(r[1]), "=r"(r[2]), "=r"(r[3]) : "r"(saddr));
}

__device__ __forceinline__ u32 smem_u32(const void* p) {
    return (u32)__cvta_generic_to_shared(p);
}

__device__ __forceinline__ void cp16(void* dst, const void* src) {
    u32 d = (u32)__cvta_generic_to_shared(dst);
    asm volatile("cp.async.cg.shared.global [%0], [%1], 16;\n" :: "r"(d), "l"(src));
}
__device__ __forceinline__ void cp_commit() { asm volatile("cp.async.commit_group;\n"); }
__device__ __forceinline__ void cp_wait1()  { asm volatile("cp.async.wait_group 1;\n"); }
__device__ __forceinline__ void cp_wait0()  { asm volatile("cp.async.wait_group 0;\n"); }

// ================================================================================
__global__ __launch_bounds__(256) void prep_x_kernel(const float* __restrict__ X) {
    int idx = blockIdx.x * 256 + threadIdx.x;
    float x = X[idx];
    __half h = __float2half(x);
    g_Xh[idx] = h;
    g_Xl[idx] = __float2half(x - __half2float(h));
}

__global__ void transpose_wqkv_kernel(const float* __restrict__ Wq,
                                      const float* __restrict__ Wk,
                                      const float* __restrict__ Wv) {
    __shared__ float tile[32][33];
    int z = blockIdx.z;
    int w = z >> 4, h = z & 15;
    const float* in = ((w == 0) ? Wq : (w == 1) ? Wk : Wv) + (size_t)h * EMB * HDIM;
    __half* oh = g_Wh + (size_t)w * 1048576 + (size_t)h * 64 * 1024;
    int e0 = blockIdx.y * 32, d0 = blockIdx.x * 32;
    for (int i = threadIdx.y; i < 32; i += 8)
        tile[i][threadIdx.x] = in[(size_t)(e0 + i) * HDIM + d0 + threadIdx.x];
    __syncthreads();
    for (int i = threadIdx.y; i < 32; i += 8)
        oh[(size_t)(d0 + i) * 1024 + e0 + threadIdx.x] = __float2half(tile[threadIdx.x][i]);
}

__global__ void transpose_wo_kernel(const float* __restrict__ Wo) {
    __shared__ float tile[32][33];
    __half* oh = g_Wh + 3u * 1048576;
    int k0 = blockIdx.y * 32, n0 = blockIdx.x * 32;
    for (int i = threadIdx.y; i < 32; i += 8)
        tile[i][threadIdx.x] = Wo[(size_t)(k0 + i) * 1024 + n0 + threadIdx.x];
    __syncthreads();
    for (int i = threadIdx.y; i < 32; i += 8)
        oh[(size_t)(n0 + i) * 1024 + k0 + threadIdx.x] = __float2half(tile[threadIdx.x][i]);
}

// ================================================================================
// fp16 2-term GEMM:  acc += Ah*Bh + Al*Bh  (== A*Bh; A.Bl term dropped, ~1.4e-4)
// smem/stage (elems): Ah@0  Al@5120  Bh@10240, stride 40/row.  2 CTAs/SM.
// ================================================================================
#define GEMM_SMEM 61440
#define ST_STRIDE 15360
#define ST_BYTES  30720

__global__ __launch_bounds__(256, 2) void gemm_kernel(int mode,
                                                      const float* __restrict__ gate,
                                                      float* __restrict__ out) {
    extern __shared__ __half sm[];
    if (mode < 0) mode = blockIdx.z;

    const int bm = blockIdx.x * 128;
    const int bn = blockIdx.y * 128;

    const __half *pAh, *pAl, *pBh;
    if (mode < 3) {
        pAh = g_Xh; pAl = g_Xl;
        pBh = g_Wh + (size_t)mode * 1048576;
    } else {
        pAh = g_Ch; pAl = g_Cl;
        pBh = g_Wh + 3u * 1048576;
    }

    const int tid = threadIdx.x;
    const int lane = tid & 31, warp = tid >> 5;
    const int wr = warp & 3, wc = warp >> 2;
    const int g = lane >> 2, c = lane & 3;

    const int lrow = tid >> 1;
    const int lseg0 = (tid & 1) * 2;

    const u32 smb = smem_u32(sm);
    const int lrA = lane & 15, lcA = (lane >> 4) << 3;
    const int lrB = (lane & 7) | ((lane >> 4) << 3);
    const int lcB = ((lane >> 3) & 1) << 3;
    const u32 offA = smb + (u32)(((wr * 32 + lrA) * 40 + lcA) * 2);
    const u32 offB = smb + 20480u + (u32)(((wc * 64 + lrB) * 40 + lcB) * 2);

    float acc[2][8][4];
#pragma unroll
    for (int mt = 0; mt < 2; mt++)
#pragma unroll
        for (int j = 0; j < 8; j++)
#pragma unroll
            for (int q = 0; q < 4; q++) acc[mt][j][q] = 0.0f;

    {
#pragma unroll
        for (int i = 0; i < 2; i++) {
            int seg = lseg0 + i;
            int off = lrow * 40 + seg * 8;
            size_t asrc = (size_t)(bm + lrow) * 1024 + seg * 8;
            size_t bsrc = (size_t)(bn + lrow) * 1024 + seg * 8;
            cp16(sm + off, pAh + asrc);
            cp16(sm + 5120 + off, pAl + asrc);
            cp16(sm + 10240 + off, pBh + bsrc);
        }
        cp_commit();
    }

    for (int it = 0; it < 32; it++) {
        const int cur = it & 1;
        if (it + 1 < 32) {
            const int k0 = (it + 1) * 32;
            __half* base = sm + (cur ^ 1) * ST_STRIDE;
#pragma unroll
            for (int i = 0; i < 2; i++) {
                int seg = lseg0 + i;
                int off = lrow * 40 + seg * 8;
                size_t asrc = (size_t)(bm + lrow) * 1024 + k0 + seg * 8;
                size_t bsrc = (size_t)(bn + lrow) * 1024 + k0 + seg * 8;
                cp16(base + off, pAh + asrc);
                cp16(base + 5120 + off, pAl + asrc);
                cp16(base + 10240 + off, pBh + bsrc);
            }
            cp_commit();
            cp_wait1();
        } else {
            cp_wait0();
        }
        __syncthreads();

        const u32 stb = (u32)(cur * ST_BYTES);
#pragma unroll
        for (int kk = 0; kk < 2; kk++) {
            u32 aH[2][4], aL[2][4];
#pragma unroll
            for (int mt = 0; mt < 2; mt++) {
                ldsm4(aH[mt], offA + stb + mt * 1280 + kk * 32);
                ldsm4(aL[mt], offA + stb + 10240 + mt * 1280 + kk * 32);
            }
#pragma unroll
            for (int jj = 0; jj < 4; jj++) {
                u32 bH[4];
                ldsm4(bH, offB + stb + jj * 1280 + kk * 32);
                // wave 1: Ah*Bh
#pragma unroll
                for (int mt = 0; mt < 2; mt++) {
                    mma16816(acc[mt][2 * jj],     aH[mt][0], aH[mt][1], aH[mt][2], aH[mt][3], bH[0], bH[1]);
                    mma16816(acc[mt][2 * jj + 1], aH[mt][0], aH[mt][1], aH[mt][2], aH[mt][3], bH[2], bH[3]);
                }
                // wave 2: Al*Bh
#pragma unroll
                for (int mt = 0; mt < 2; mt++) {
                    mma16816(acc[mt][2 * jj],     aL[mt][0], aL[mt][1], aL[mt][2], aL[mt][3], bH[0], bH[1]);
                    mma16816(acc[mt][2 * jj + 1], aL[mt][0], aL[mt][1], aL[mt][2], aL[mt][3], bH[2], bH[3]);
                }
            }
        }
        __syncthreads();
    }

    // ---------------- epilogues ----------------
    if (mode == 3) {
        int cnt = 0;
#pragma unroll
        for (int i = 0; i < NHEAD; i++) cnt += (gate[i] > GATE_EPS) ? 1 : 0;
        float scale = (cnt > 0) ? 1.0f / fmaxf(1.0f, (float)cnt / (float)NHEAD) : 1.0f;
#pragma unroll
        for (int mt = 0; mt < 2; mt++) {
            int row = bm + wr * 32 + mt * 16 + g;
#pragma unroll
            for (int j = 0; j < 8; j++) {
                int n0 = bn + wc * 64 + j * 8 + 2 * c;
                float2 v0 = make_float2(acc[mt][j][0] * scale, acc[mt][j][1] * scale);
                float2 v1 = make_float2(acc[mt][j][2] * scale, acc[mt][j][3] * scale);
                *(float2*)&out[(size_t)row * 1024 + n0] = v0;
                *(float2*)&out[(size_t)(row + 8) * 1024 + n0] = v1;
            }
        }
    } else if (mode == 2) {
        // V: transposed [bh][d][s], hi only
#pragma unroll
        for (int mt = 0; mt < 2; mt++) {
            int row = bm + wr * 32 + mt * 16 + g;
            int b = row >> 11, s = row & (SEQ - 1);
#pragma unroll
            for (int j = 0; j < 8; j++) {
                int n0 = bn + wc * 64 + j * 8 + 2 * c;
                int h = n0 >> 6, d = n0 & 63;
                size_t vb = (size_t)(b * 16 + h) * 64;
                g_Vh[(vb + d) * 2048 + s]         = __float2half(acc[mt][j][0]);
                g_Vh[(vb + d + 1) * 2048 + s]     = __float2half(acc[mt][j][1]);
                g_Vh[(vb + d) * 2048 + s + 8]     = __float2half(acc[mt][j][2]);
                g_Vh[(vb + d + 1) * 2048 + s + 8] = __float2half(acc[mt][j][3]);
            }
        }
    } else if (mode == 1) {
        // K: [bh][s][d], hi only
#pragma unroll
        for (int mt = 0; mt < 2; mt++) {
            int row = bm + wr * 32 + mt * 16 + g;
            int b = row >> 11, s = row & (SEQ - 1);
#pragma unroll
            for (int j = 0; j < 8; j++) {
                int n0 = bn + wc * 64 + j * 8 + 2 * c;
                int h = n0 >> 6, d = n0 & 63;
                size_t base = (((size_t)(b * 16 + h)) * SEQ + s) * 64 + d;
                __half2 p0 = __halves2half2(__float2half(acc[mt][j][0]), __float2half(acc[mt][j][1]));
                __half2 p1 = __halves2half2(__float2half(acc[mt][j][2]), __float2half(acc[mt][j][3]));
                *(__half2*)&g_Kh[base] = p0;
                *(__half2*)&g_Kh[base + 8 * 64] = p1;
            }
        }
    } else {
        // Q: hi/lo
#pragma unroll
        for (int mt = 0; mt < 2; mt++) {
            int row = bm + wr * 32 + mt * 16 + g;
            int b = row >> 11, s = row & (SEQ - 1);
#pragma unroll
            for (int j = 0; j < 8; j++) {
                int n0 = bn + wc * 64 + j * 8 + 2 * c;
                int h = n0 >> 6, d = n0 & 63;
                size_t base = (((size_t)(b * 16 + h)) * SEQ + s) * 64 + d;
                u32 hp, lp;
                split_pair(acc[mt][j][0], acc[mt][j][1], hp, lp);
                *(u32*)&g_Qh[base] = hp;
                *(u32*)&g_Ql[base] = lp;
                split_pair(acc[mt][j][2], acc[mt][j][3], hp, lp);
                *(u32*)&g_Qh[base + 8 * 64] = hp;
                *(u32*)&g_Ql[base + 8 * 64] = lp;
            }
        }
    }
}

// ================================================================================
// Fused flash attention, fp16 2-term:  S = (Qh+Ql)*Kh ;  O += (Ph+Pl)*Vh
// smem bytes: Qh@0(18432) Ql@18432 | Kh stages @36864 (2x18432)
//             Vh stages @73728 (2x17408) | mask @108544 (2x512B)
// ================================================================================
#define QK_STRIDE 72
#define V_STRIDE  136
#define FLASH_SMEM 109568

__global__ __launch_bounds__(256, 1) void flash_kernel(const float* __restrict__ mask,
                                                       const float* __restrict__ gate) {
    extern __shared__ char smraw[];
    __half* S = (__half*)smraw;
    float* maskS = (float*)(smraw + 108544);

    const int bm = blockIdx.x * 128;
    const int bh = blockIdx.y;
    const int b = bh >> 4, h = bh & 15;

    const int tid = threadIdx.x;
    const int lane = tid & 31, warp = tid >> 5;
    const int g = lane >> 2, c = lane & 3;
    const int mr = warp * 16;

    const u32 sb = smem_u32(smraw);
    const int lrA = lane & 15, lcA = (lane >> 4) << 3;
    const int lrB = (lane & 7) | ((lane >> 4) << 3);
    const int lcB = ((lane >> 3) & 1) << 3;
    const u32 qAddrH = sb + (u32)((mr + lrA) * 144 + lcA * 2);
    const u32 qAddrL = qAddrH + 18432u;
    const u32 kAddrH = sb + 36864u + (u32)(lrB * 144 + lcB * 2);
    const u32 vAddrH = sb + 73728u + (u32)(lrB * 272 + lcB * 2);

    // prologue: Q (hi/lo) + stage 0 K/V/mask
    {
        const size_t qbase = ((size_t)bh * SEQ + bm) * 64;
#pragma unroll
        for (int i = 0; i < 4; i++) {
            int idx = tid + i * 256;
            int row = idx >> 3, seg = idx & 7;
            cp16(S + row * QK_STRIDE + seg * 8, g_Qh + qbase + (size_t)row * 64 + seg * 8);
            cp16(S + 9216 + row * QK_STRIDE + seg * 8, g_Ql + qbase + (size_t)row * 64 + seg * 8);
        }
        const size_t kbase = (size_t)bh * SEQ * 64;
#pragma unroll
        for (int i = 0; i < 4; i++) {
            int idx = tid + i * 256;
            int row = idx >> 3, seg = idx & 7;
            cp16(S + 18432 + row * QK_STRIDE + seg * 8, g_Kh + kbase + (size_t)row * 64 + seg * 8);
        }
        const size_t vbase = (size_t)bh * 64 * 2048;
#pragma unroll
        for (int i = 0; i < 4; i++) {
            int idx = tid + i * 256;
            int d = idx >> 4, seg = idx & 15;
            cp16(S + 36864 + d * V_STRIDE + seg * 8, g_Vh + vbase + (size_t)d * 2048 + seg * 8);
        }
        if (tid < 32) cp16(maskS + tid * 4, mask + b * SEQ + tid * 4);
        cp_commit();
    }
    cp_wait0();
    __syncthreads();

    // hoist Q fragments
    u32 qH[4][4], qL[4][4];
#pragma unroll
    for (int kk = 0; kk < 4; kk++) {
        ldsm4(qH[kk], qAddrH + kk * 32);
        ldsm4(qL[kk], qAddrL + kk * 32);
    }

    float o[8][4];
#pragma unroll
    for (int j = 0; j < 8; j++)
#pragma unroll
        for (int q = 0; q < 4; q++) o[j][q] = 0.0f;
    float m0 = -1e30f, m1 = -1e30f, l0 = 0.0f, l1 = 0.0f;

    for (int it = 0; it < 16; it++) {
        const int cur = it & 1;
        if (it + 1 < 16) {
            const int st = cur ^ 1;
            const int t0 = (it + 1) * 128;
            const size_t kbase = ((size_t)bh * SEQ + t0) * 64;
#pragma unroll
            for (int i = 0; i < 4; i++) {
                int idx = tid + i * 256;
                int row = idx >> 3, seg = idx & 7;
                cp16(S + 18432 + st * 9216 + row * QK_STRIDE + seg * 8,
                     g_Kh + kbase + (size_t)row * 64 + seg * 8);
            }
            const size_t vbase = (size_t)bh * 64 * 2048 + t0;
#pragma unroll
            for (int i = 0; i < 4; i++) {
                int idx = tid + i * 256;
                int d = idx >> 4, seg = idx & 15;
                cp16(S + 36864 + st * 8704 + d * V_STRIDE + seg * 8,
                     g_Vh + vbase + (size_t)d * 2048 + seg * 8);
            }
            if (tid < 32) cp16(maskS + st * 128 + tid * 4, mask + b * SEQ + t0 + tid * 4);
            cp_commit();
            cp_wait1();
        } else {
            cp_wait0();
        }
        __syncthreads();

        const u32 kStH = kAddrH + (u32)(cur * 18432);
        const u32 vStH = vAddrH + (u32)(cur * 17408);
        const float* mk = maskS + cur * 128;

        float s[16][4];
#pragma unroll
        for (int j = 0; j < 16; j++)
#pragma unroll
            for (int q = 0; q < 4; q++) s[j][q] = 0.0f;

#pragma unroll
        for (int kk = 0; kk < 4; kk++) {
#pragma unroll
            for (int jj = 0; jj < 8; jj += 2) {
                u32 kh0[4], kh1[4];
                ldsm4(kh0, kStH + jj * 2304 + kk * 32);
                ldsm4(kh1, kStH + (jj + 1) * 2304 + kk * 32);
                float* s0 = s[2 * jj];
                float* s1 = s[2 * jj + 1];
                float* s2 = s[2 * jj + 2];
                float* s3 = s[2 * jj + 3];
                // wave 1: Qh*Kh
                mma16816(s0, qH[kk][0], qH[kk][1], qH[kk][2], qH[kk][3], kh0[0], kh0[1]);
                mma16816(s1, qH[kk][0], qH[kk][1], qH[kk][2], qH[kk][3], kh0[2], kh0[3]);
                mma16816(s2, qH[kk][0], qH[kk][1], qH[kk][2], qH[kk][3], kh1[0], kh1[1]);
                mma16816(s3, qH[kk][0], qH[kk][1], qH[kk][2], qH[kk][3], kh1[2], kh1[3]);
                // wave 2: Ql*Kh
                mma16816(s0, qL[kk][0], qL[kk][1], qL[kk][2], qL[kk][3], kh0[0], kh0[1]);
                mma16816(s1, qL[kk][0], qL[kk][1], qL[kk][2], qL[kk][3], kh0[2], kh0[3]);
                mma16816(s2, qL[kk][0], qL[kk][1], qL[kk][2], qL[kk][3], kh1[0], kh1[1]);
                mma16816(s3, qL[kk][0], qL[kk][1], qL[kk][2], qL[kk][3], kh1[2], kh1[3]);
            }
        }

#pragma unroll
        for (int j = 0; j < 16; j++) {
            float mk0 = mk[j * 8 + 2 * c];
            float mk1 = mk[j * 8 + 2 * c + 1];
            s[j][0] = s[j][0] * 0.125f + mk0;
            s[j][1] = s[j][1] * 0.125f + mk1;
            s[j][2] = s[j][2] * 0.125f + mk0;
            s[j][3] = s[j][3] * 0.125f + mk1;
        }

        float mt0 = -1e30f, mt1 = -1e30f;
#pragma unroll
        for (int j = 0; j < 16; j++) {
            mt0 = fmaxf(mt0, fmaxf(s[j][0], s[j][1]));
            mt1 = fmaxf(mt1, fmaxf(s[j][2], s[j][3]));
        }
        mt0 = fmaxf(mt0, __shfl_xor_sync(0xffffffffu, mt0, 1));
        mt0 = fmaxf(mt0, __shfl_xor_sync(0xffffffffu, mt0, 2));
        mt1 = fmaxf(mt1, __shfl_xor_sync(0xffffffffu, mt1, 1));
        mt1 = fmaxf(mt1, __shfl_xor_sync(0xffffffffu, mt1, 2));
        float mn0 = fmaxf(m0, mt0), mn1 = fmaxf(m1, mt1);
        float al0 = __expf(m0 - mn0), al1 = __expf(m1 - mn1);
        m0 = mn0; m1 = mn1;

        float rs0 = 0.0f, rs1 = 0.0f;
#pragma unroll
        for (int j = 0; j < 16; j++) {
            s[j][0] = __expf(s[j][0] - mn0); rs0 += s[j][0];
            s[j][1] = __expf(s[j][1] - mn0); rs0 += s[j][1];
            s[j][2] = __expf(s[j][2] - mn1); rs1 += s[j][2];
            s[j][3] = __expf(s[j][3] - mn1); rs1 += s[j][3];
        }
        rs0 += __shfl_xor_sync(0xffffffffu, rs0, 1);
        rs0 += __shfl_xor_sync(0xffffffffu, rs0, 2);
        rs1 += __shfl_xor_sync(0xffffffffu, rs1, 1);
        rs1 += __shfl_xor_sync(0xffffffffu, rs1, 2);
        l0 = l0 * al0 + rs0;
        l1 = l1 * al1 + rs1;
#pragma unroll
        for (int j = 0; j < 8; j++) {
            o[j][0] *= al0; o[j][1] *= al0;
            o[j][2] *= al1; o[j][3] *= al1;
        }

        // ---- O += P V : (Ph+Pl)*Vh ----
#pragma unroll
        for (int kk = 0; kk < 8; kk++) {
            u32 pa0, pa1, pa2, pa3, pb0, pb1, pb2, pb3;
            split_pair(s[2 * kk][0], s[2 * kk][1], pa0, pb0);
            split_pair(s[2 * kk][2], s[2 * kk][3], pa1, pb1);
            split_pair(s[2 * kk + 1][0], s[2 * kk + 1][1], pa2, pb2);
            split_pair(s[2 * kk + 1][2], s[2 * kk + 1][3], pa3, pb3);
#pragma unroll
            for (int jj = 0; jj < 4; jj += 2) {
                u32 vh0[4], vh1[4];
                ldsm4(vh0, vStH + jj * 4352 + kk * 32);
                ldsm4(vh1, vStH + (jj + 1) * 4352 + kk * 32);
                float* o0 = o[2 * jj];
                float* o1 = o[2 * jj + 1];
                float* o2 = o[2 * jj + 2];
                float* o3 = o[2 * jj + 3];
                // wave 1: Ph*Vh
                mma16816(o0, pa0, pa1, pa2, pa3, vh0[0], vh0[1]);
                mma16816(o1, pa0, pa1, pa2, pa3, vh0[2], vh0[3]);
                mma16816(o2, pa0, pa1, pa2, pa3, vh1[0], vh1[1]);
                mma16816(o3, pa0, pa1, pa2, pa3, vh1[2], vh1[3]);
                // wave 2: Pl*Vh
                mma16816(o0, pb0, pb1, pb2, pb3, vh0[0], vh0[1]);
                mma16816(o1, pb0, pb1, pb2, pb3, vh0[2], vh0[3]);
                mma16816(o2, pb0, pb1, pb2, pb3, vh1[0], vh1[1]);
                mma16816(o3, pb0, pb1, pb2, pb3, vh1[2], vh1[3]);
            }
        }
        __syncthreads();
    }

    // ---- epilogue: (O / l) * eff_gate -> hi/lo fp16 at [b][s][h*64+d] ----
    float gv = gate[h];
    float eff = (gv >= GATE_EPS) ? gv : 0.0f;
    float inv0 = eff / l0, inv1 = eff / l1;
    int row0 = bm + mr + g;
#pragma unroll
    for (int j = 0; j < 8; j++) {
        int e0 = h * 64 + j * 8 + 2 * c;
        size_t base0 = ((size_t)b * SEQ + row0) * 1024 + e0;
        size_t base1 = ((size_t)b * SEQ + row0 + 8) * 1024 + e0;
        u32 hp, lp;
        split_pair(o[j][0] * inv0, o[j][1] * inv0, hp, lp);
        *(u32*)&g_Ch[base0] = hp;
        *(u32*)&g_Cl[base0] = lp;
        split_pair(o[j][2] * inv1, o[j][3] * inv1, hp, lp);
        *(u32*)&g_Ch[base1] = hp;
        *(u32*)&g_Cl[base1] = lp;
    }
}

// ================================================================================
extern "C" void kernel_launch(void* const* d_in, const int* in_sizes, int n_in,
                              void* d_out, int out_size) {
    const float* X    = (const float*)d_in[0];
    const float* mask = (const float*)d_in[1];
    const float* Wq   = (const float*)d_in[2];
    const float* Wk   = (const float*)d_in[3];
    const float* Wv   = (const float*)d_in[4];
    const float* Wo   = (const float*)d_in[5];
    const float* gate = (const float*)d_in[6];
    float* out = (float*)d_out;

    cudaFuncSetAttribute(gemm_kernel, cudaFuncAttributeMaxDynamicSharedMemorySize, GEMM_SMEM);
    cudaFuncSetAttribute(flash_kernel, cudaFuncAttributeMaxDynamicSharedMemorySize, FLASH_SMEM);

    prep_x_kernel<<<16384, 256>>>(X);
    transpose_wqkv_kernel<<<dim3(2, 32, 48), dim3(32, 8)>>>(Wq, Wk, Wv);
    transpose_wo_kernel<<<dim3(32, 32), dim3(32, 8)>>>(Wo);
    gemm_kernel<<<dim3(32, 8, 3), 256, GEMM_SMEM>>>(-1, gate, out);   // QKV
    flash_kernel<<<dim3(16, 32), 256, FLASH_SMEM>>>(mask, gate);
    gemm_kernel<<<dim3(32, 8, 1), 256, GEMM_SMEM>>>(3, gate, out);    // O proj
}